// round 14
// baseline (speedup 1.0000x reference)
#include <cuda_runtime.h>
#include <cuda_bf16.h>
#include <math.h>
#include <float.h>

#define NB 4
#define NP 4096
#define NC 256
#define NK 16
#define NPTS (NB*NP)      /* 16384 */
#define NROWS (NPTS*NK)   /* 262144 */

// ---------------- scratch (device globals; no allocation) ----------------
__device__ float g_q [NPTS*NC];
__device__ float g_kf[NPTS*NC];
__device__ float g_vf[NPTS*NC];
__device__ int   g_idx[NROWS];
__device__ float g_u [NROWS*3];
__device__ float g_h [NROWS*NC];
__device__ float g_h2[NROWS*NC];
__device__ float g_bnd[6];
__device__ float g_partd[512*6];
__device__ float g_ps1[512*NC];
__device__ float g_pq1[512*NC];
__device__ float g_ps2[2048*NC];
__device__ float g_pq2[2048*NC];
__device__ float g_bn1[2*NC];
__device__ float g_bn2[2*NC];
__device__ __nv_bfloat16 g_bh1[NC*NC], g_bl1[NC*NC];
__device__ __nv_bfloat16 g_bh2[NC*NC], g_bl2[NC*NC];
__device__ __nv_bfloat16 g_bhq[NC*NC], g_blq[NC*NC];
__device__ __nv_bfloat16 g_bhk[NC*NC], g_blk[NC*NC];
__device__ __nv_bfloat16 g_bhv[NC*NC], g_blv[NC*NC];

// ---------------- exact-rounding helpers for KNN ----------------
__device__ __forceinline__ float sq3_exact(float x, float y, float z){
    return __fadd_rn(__fadd_rn(__fmul_rn(x,x), __fmul_rn(y,y)), __fmul_rn(z,z));
}
__device__ __forceinline__ float dist_exact(float qx,float qy,float qz,float qw,
                                            float px,float py,float pz,float pw){
    float dot = __fmaf_rn(qz, pz, __fmaf_rn(qy, py, __fmul_rn(qx, px)));
    return __fsub_rn(__fadd_rn(qw, pw), __fmul_rn(2.0f, dot));
}

// ---------------- KNN ----------------
__global__ __launch_bounds__(512) void knn_kernel(const float* __restrict__ xyz)
{
    constexpr int CH = 2048;
    __shared__ float4 pts[CH];
    int b = blockIdx.y;
    const float* xb = xyz + b*NP*3;
    int warp = threadIdx.x >> 5, lane = threadIdx.x & 31;
    int n = blockIdx.x*16 + warp;
    float qx = xb[n*3+0], qy = xb[n*3+1], qz = xb[n*3+2];
    float qw = sq3_exact(qx, qy, qz);
    float dl[NK]; int il[NK];
#pragma unroll
    for (int j=0;j<NK;j++){ dl[j]=FLT_MAX; il[j]=0x7fffffff; }

    for (int c0=0;c0<NP;c0+=CH){
        __syncthreads();
        for (int i=threadIdx.x;i<CH;i+=512){
            int m=c0+i;
            float x=xb[m*3],y=xb[m*3+1],z=xb[m*3+2];
            pts[i]=make_float4(x,y,z, sq3_exact(x,y,z));
        }
        __syncthreads();
        for (int i=lane;i<CH;i+=32){
            float4 p=pts[i];
            int m=c0+i;
            float d = dist_exact(qx,qy,qz,qw, p.x,p.y,p.z,p.w);
            if (d < dl[NK-1] || (d==dl[NK-1] && m<il[NK-1])){
                dl[NK-1]=d; il[NK-1]=m;
#pragma unroll
                for (int j=NK-1;j>0;j--){
                    bool sw = dl[j]<dl[j-1] || (dl[j]==dl[j-1] && il[j]<il[j-1]);
                    float t0 = sw? dl[j-1]:dl[j];
                    float t1 = sw? dl[j]:dl[j-1];
                    int   i0 = sw? il[j-1]:il[j];
                    int   i1 = sw? il[j]:il[j-1];
                    dl[j]=t0; dl[j-1]=t1; il[j]=i0; il[j-1]=i1;
                }
            }
        }
    }
    for (int r=0;r<NK;r++){
        float cd = dl[0]; int ci = il[0];
        float rd = cd;    int ri = ci;
#pragma unroll
        for (int off=16; off>0; off>>=1){
            float od = __shfl_down_sync(0xffffffffu, rd, off);
            int   oi = __shfl_down_sync(0xffffffffu, ri, off);
            if (od<rd || (od==rd && oi<ri)){ rd=od; ri=oi; }
        }
        rd = __shfl_sync(0xffffffffu, rd, 0);
        ri = __shfl_sync(0xffffffffu, ri, 0);
        if (lane==0) g_idx[(b*NP+n)*NK + r] = ri;
        if (cd==rd && ci==ri){
#pragma unroll
            for (int j=0;j<NK-1;j++){ dl[j]=dl[j+1]; il[j]=il[j+1]; }
            dl[NK-1]=FLT_MAX; il[NK-1]=0x7fffffff;
        }
    }
}

// ---------------- d-path BN stats ----------------
__global__ __launch_bounds__(256) void dstat_kernel(const float* __restrict__ xyz,
                                                    const float* __restrict__ d1w,
                                                    const float* __restrict__ d1b)
{
    float s[3]={0.f,0.f,0.f}, sq[3]={0.f,0.f,0.f};
    int stride = gridDim.x*blockDim.x;
    for (int it = blockIdx.x*blockDim.x+threadIdx.x; it < NROWS; it += stride){
        int pt = it >> 4;
        int b  = pt >> 12;
        int j  = g_idx[it];
        float r0 = xyz[pt*3+0] - xyz[(b*NP+j)*3+0];
        float r1 = xyz[pt*3+1] - xyz[(b*NP+j)*3+1];
        float r2 = xyz[pt*3+2] - xyz[(b*NP+j)*3+2];
#pragma unroll
        for (int d=0;d<3;d++){
            float t = r0*d1w[d] + r1*d1w[3+d] + r2*d1w[6+d] + d1b[d];
            s[d]+=t; sq[d]+=t*t;
        }
    }
    __shared__ float red[256];
    for (int q=0;q<6;q++){
        red[threadIdx.x] = (q<3)? s[q] : sq[q-3];
        __syncthreads();
        for (int st=128; st; st>>=1){
            if (threadIdx.x<st) red[threadIdx.x]+=red[threadIdx.x+st];
            __syncthreads();
        }
        if (threadIdx.x==0) g_partd[blockIdx.x*6+q]=red[0];
        __syncthreads();
    }
}

__global__ void dfin_kernel(const float* __restrict__ g, const float* __restrict__ beta)
{
    int d = threadIdx.x;
    if (d>=3) return;
    double s=0.0,q=0.0;
    for (int i=0;i<512;i++){ s+=g_partd[i*6+d]; q+=g_partd[i*6+3+d]; }
    double m = s/(double)NROWS;
    double v = q/(double)NROWS - m*m;
    double sc = (double)g[d] / sqrt(v+1e-5);
    g_bnd[d]   = (float)sc;
    g_bnd[3+d] = (float)((double)beta[d] - m*sc);
}

// ---------------- weight prep (all 5 matrices, one launch) ----------------
__global__ void bprep5_kernel(const float* __restrict__ g1w, const float* __restrict__ g2w,
                              const float* __restrict__ wq,  const float* __restrict__ wk,
                              const float* __restrict__ wv)
{
    int k = blockIdx.x, n = threadIdx.x;
    const float* W; __nv_bfloat16 *H, *L;
    switch (blockIdx.y){
        case 0: W=g1w; H=g_bh1; L=g_bl1; break;
        case 1: W=g2w; H=g_bh2; L=g_bl2; break;
        case 2: W=wq;  H=g_bhq; L=g_blq; break;
        case 3: W=wk;  H=g_bhk; L=g_blk; break;
        default:W=wv;  H=g_bhv; L=g_blv; break;
    }
    float w = W[k*NC+n];
    __nv_bfloat16 h = __float2bfloat16_rn(w);
    H[n*NC+k] = h;
    L[n*NC+k] = __float2bfloat16_rn(w - __bfloat162float(h));
}

// ---------------- HMMA helpers ----------------
__device__ __forceinline__ void mma_bf16(float* c, const unsigned* a, const unsigned* b){
    asm volatile(
      "mma.sync.aligned.m16n8k16.row.col.f32.bf16.bf16.f32 "
      "{%0,%1,%2,%3}, {%4,%5,%6,%7}, {%8,%9}, {%0,%1,%2,%3};"
      : "+f"(c[0]),"+f"(c[1]),"+f"(c[2]),"+f"(c[3])
      : "r"(a[0]),"r"(a[1]),"r"(a[2]),"r"(a[3]), "r"(b[0]),"r"(b[1]));
}
__device__ __forceinline__ void ldmx4(unsigned* r, unsigned addr){
    asm volatile("ldmatrix.sync.aligned.m8n8.x4.shared.b16 {%0,%1,%2,%3}, [%4];"
                 : "=r"(r[0]),"=r"(r[1]),"=r"(r[2]),"=r"(r[3]) : "r"(addr));
}
__device__ __forceinline__ void cpa16(unsigned dst, const void* src){
    asm volatile("cp.async.cg.shared.global [%0], [%1], 16;" :: "r"(dst), "l"(src));
}
#define CPA_COMMIT asm volatile("cp.async.commit_group;" ::: "memory")
#define CPA_WAIT0  asm volatile("cp.async.wait_group 0;" ::: "memory")

#define KC 32           /* K-chunk */
#define RSTRIDE 40      /* bf16 tile row stride in halves: 80B, ldmatrix conflict-free */
#define ATILE 10240     /* bytes per 128xKC bf16 tile */
#define AFSTRIDE 36     /* fp32 A staging row stride in words */
// dynamic smem layout
#define SM_ASH 0
#define SM_ASL ATILE
#define SM_BH(buf) (2*ATILE + (buf)*2*ATILE)
#define SM_BL(buf) (3*ATILE + (buf)*2*ATILE)
#define SM_AF(buf) (6*ATILE + (buf)*(128*AFSTRIDE*4))
#define SM_TOTAL (6*ATILE + 2*(128*AFSTRIDE*4))   /* 98304 */

// Shared mainloop: cp.async double-buffered pipeline; interleaved bf16x3 compute.
// Per k-step: load Ah/Al fragments once, B hi/lo per n-pair, fire 3 products from regs.
template<bool BNRELU>
__device__ __forceinline__ void gemm_mainloop(
    const float* __restrict__ A, const __nv_bfloat16* __restrict__ Bh,
    const __nv_bfloat16* __restrict__ Bl, const float* __restrict__ bnp,
    char* dsm, size_t rowbase, int ncb, int tid, int wm, int wn,
    float acc[2][8][4])
{
    int lane = tid & 31;
    int lr = tid >> 1;
    int cg = (tid & 1) * 16;
    int q3 = lane >> 3, rl = lane & 7;
    unsigned sb = (unsigned)__cvta_generic_to_shared(dsm);
    unsigned aoffA = (unsigned)(((wm*32 + (q3&1)*8 + rl) * RSTRIDE + (q3>>1)*8) * 2);
    unsigned aoffB = (unsigned)(((wn*64 + (q3>>1)*8 + rl) * RSTRIDE + (q3&1)*8) * 2);

    const float*         asrc0 = A  + (rowbase + lr)*256 + cg;
    const __nv_bfloat16* bhs0  = Bh + (size_t)(ncb + lr)*256 + cg;
    const __nv_bfloat16* bls0  = Bl + (size_t)(ncb + lr)*256 + cg;
    unsigned adst_r = (unsigned)((lr*AFSTRIDE + cg)*4);
    unsigned bdst_r = (unsigned)((lr*RSTRIDE  + cg)*2);

    // prologue: chunk 0 -> buffers 0
    {
        unsigned ad = sb + SM_AF(0) + adst_r;
        cpa16(ad,    asrc0);     cpa16(ad+16, asrc0+4);
        cpa16(ad+32, asrc0+8);   cpa16(ad+48, asrc0+12);
        unsigned bh = sb + SM_BH(0) + bdst_r;
        unsigned bl = sb + SM_BL(0) + bdst_r;
        cpa16(bh, bhs0); cpa16(bh+16, bhs0+8);
        cpa16(bl, bls0); cpa16(bl+16, bls0+8);
        CPA_COMMIT;
    }

    for (int ic = 0; ic < 8; ic++){
        int buf = ic & 1;
        CPA_WAIT0;
        __syncthreads();

        if (ic < 7){
            int kc1 = (ic+1)*KC;
            unsigned ad = sb + SM_AF(buf^1) + adst_r;
            const float* as = asrc0 + kc1;
            cpa16(ad,    as);    cpa16(ad+16, as+4);
            cpa16(ad+32, as+8);  cpa16(ad+48, as+12);
            unsigned bh = sb + SM_BH(buf^1) + bdst_r;
            unsigned bl = sb + SM_BL(buf^1) + bdst_r;
            cpa16(bh, bhs0 + kc1); cpa16(bh+16, bhs0 + kc1 + 8);
            cpa16(bl, bls0 + kc1); cpa16(bl+16, bls0 + kc1 + 8);
            CPA_COMMIT;
        }

        // convert A chunk ic: smem fp32 -> bnrelu -> bf16 hi/lo tiles
        {
            int kc0 = ic*KC;
            const float* af = (const float*)(dsm + SM_AF(buf)) + lr*AFSTRIDE + cg;
            float v[16];
            *(float4*)(v)    = *(const float4*)(af);
            *(float4*)(v+4)  = *(const float4*)(af+4);
            *(float4*)(v+8)  = *(const float4*)(af+8);
            *(float4*)(v+12) = *(const float4*)(af+12);
            unsigned hh[8], ll[8];
#pragma unroll
            for (int p=0;p<8;p++){
                float a0 = v[p*2], a1 = v[p*2+1];
                if (BNRELU){
                    int c = kc0 + cg + p*2;
                    a0 = fmaxf(0.f, fmaf(a0, bnp[c],   bnp[256+c]));
                    a1 = fmaxf(0.f, fmaf(a1, bnp[c+1], bnp[257+c]));
                }
                __nv_bfloat16 h0 = __float2bfloat16_rn(a0);
                __nv_bfloat16 h1 = __float2bfloat16_rn(a1);
                __nv_bfloat16 l0 = __float2bfloat16_rn(a0 - __bfloat162float(h0));
                __nv_bfloat16 l1 = __float2bfloat16_rn(a1 - __bfloat162float(h1));
                hh[p] = (unsigned)__bfloat16_as_ushort(h0) | ((unsigned)__bfloat16_as_ushort(h1)<<16);
                ll[p] = (unsigned)__bfloat16_as_ushort(l0) | ((unsigned)__bfloat16_as_ushort(l1)<<16);
            }
            unsigned short (*AsH)[RSTRIDE] = (unsigned short(*)[RSTRIDE])(dsm + SM_ASH);
            unsigned short (*AsL)[RSTRIDE] = (unsigned short(*)[RSTRIDE])(dsm + SM_ASL);
            *(uint4*)&AsH[lr][cg]   = make_uint4(hh[0],hh[1],hh[2],hh[3]);
            *(uint4*)&AsH[lr][cg+8] = make_uint4(hh[4],hh[5],hh[6],hh[7]);
            *(uint4*)&AsL[lr][cg]   = make_uint4(ll[0],ll[1],ll[2],ll[3]);
            *(uint4*)&AsL[lr][cg+8] = make_uint4(ll[4],ll[5],ll[6],ll[7]);
        }
        __syncthreads();

        unsigned aASH = sb + SM_ASH, aASL = sb + SM_ASL;
        unsigned aBH  = sb + SM_BH(buf), aBL = sb + SM_BL(buf);
#pragma unroll
        for (int ks=0; ks<KC; ks+=16){
            unsigned ah[2][4], al[2][4];
#pragma unroll
            for (int mt=0;mt<2;mt++){
                unsigned o = aoffA + (unsigned)((mt*16*RSTRIDE + ks)*2);
                ldmx4(ah[mt], aASH + o);
                ldmx4(al[mt], aASL + o);
            }
#pragma unroll
            for (int np2=0; np2<2; np2++){
                unsigned bh[2][4], bl[2][4];
#pragma unroll
                for (int j=0;j<2;j++){
                    unsigned o = aoffB + (unsigned)(((np2*2+j)*16*RSTRIDE + ks)*2);
                    ldmx4(bh[j], aBH + o);
                    ldmx4(bl[j], aBL + o);
                }
                // product-major: AhBh, AhBl, AlBh (same-acc distance = 8 mmas)
#pragma unroll
                for (int j=0;j<2;j++)
#pragma unroll
                    for (int mt=0;mt<2;mt++){
                        mma_bf16(acc[mt][2*(np2*2+j)],   ah[mt], bh[j]);
                        mma_bf16(acc[mt][2*(np2*2+j)+1], ah[mt], bh[j]+2);
                    }
#pragma unroll
                for (int j=0;j<2;j++)
#pragma unroll
                    for (int mt=0;mt<2;mt++){
                        mma_bf16(acc[mt][2*(np2*2+j)],   ah[mt], bl[j]);
                        mma_bf16(acc[mt][2*(np2*2+j)+1], ah[mt], bl[j]+2);
                    }
#pragma unroll
                for (int j=0;j<2;j++)
#pragma unroll
                    for (int mt=0;mt<2;mt++){
                        mma_bf16(acc[mt][2*(np2*2+j)],   al[mt], bh[j]);
                        mma_bf16(acc[mt][2*(np2*2+j)+1], al[mt], bh[j]+2);
                    }
            }
        }
    }
}

// ---------------- GEMM (qkv / gamma1): store C, optional BN+fused stats ----------------
template<bool BNRELU, bool STATS>
__global__ __launch_bounds__(256, 2) void gemm_mma_kernel(
    const float* __restrict__ A,
    const __nv_bfloat16* __restrict__ Bh, const __nv_bfloat16* __restrict__ Bl,
    const float* __restrict__ bias, const float* __restrict__ bnp,
    float* __restrict__ C, float* __restrict__ psum, float* __restrict__ psq)
{
    extern __shared__ __align__(128) char dsm[];

    int tid = threadIdx.x, wid = tid >> 5, lane = tid & 31;
    int g = lane >> 2, t = lane & 3;
    int wm = wid & 3, wn = wid >> 2;
    const size_t rowbase = (size_t)blockIdx.x * 128;
    const int ncb = blockIdx.y * 128;

    float acc[2][8][4];
#pragma unroll
    for (int mt=0;mt<2;mt++)
#pragma unroll
        for (int nt=0;nt<8;nt++)
#pragma unroll
            for (int i=0;i<4;i++) acc[mt][nt][i]=0.f;

    gemm_mainloop<BNRELU>(A, Bh, Bl, bnp, dsm, rowbase, ncb, tid, wm, wn, acc);

#pragma unroll
    for (int nt=0;nt<8;nt++){
        int col = ncb + wn*64 + nt*8 + 2*t;
        float b0 = bias[col], b1 = bias[col+1];
#pragma unroll
        for (int mt=0;mt<2;mt++){
            acc[mt][nt][0]+=b0; acc[mt][nt][1]+=b1;
            acc[mt][nt][2]+=b0; acc[mt][nt][3]+=b1;
        }
    }
#pragma unroll
    for (int nt=0;nt<8;nt++){
        int col = ncb + wn*64 + nt*8 + 2*t;
#pragma unroll
        for (int mt=0;mt<2;mt++){
            size_t row = rowbase + wm*32 + mt*16 + g;
            *(float2*)&C[row*256 + col]     = make_float2(acc[mt][nt][0], acc[mt][nt][1]);
            *(float2*)&C[(row+8)*256 + col] = make_float2(acc[mt][nt][2], acc[mt][nt][3]);
        }
    }

    if (STATS){
        __syncthreads();
        float* sS = (float*)dsm;              // [4][128]
        float* sQ = sS + 512;
#pragma unroll
        for (int nt=0;nt<8;nt++){
            float s0=0.f,q0=0.f,s1=0.f,q1=0.f;
#pragma unroll
            for (int mt=0;mt<2;mt++){
                float v0=acc[mt][nt][0], v2=acc[mt][nt][2];
                float v1=acc[mt][nt][1], v3=acc[mt][nt][3];
                s0 += v0+v2;  q0 += v0*v0+v2*v2;
                s1 += v1+v3;  q1 += v1*v1+v3*v3;
            }
#pragma unroll
            for (int off=16; off>=4; off>>=1){
                s0 += __shfl_down_sync(0xffffffffu, s0, off);
                q0 += __shfl_down_sync(0xffffffffu, q0, off);
                s1 += __shfl_down_sync(0xffffffffu, s1, off);
                q1 += __shfl_down_sync(0xffffffffu, q1, off);
            }
            if (lane < 4){
                int c = wn*64 + nt*8 + 2*lane;
                sS[wm*128 + c]     = s0;  sS[wm*128 + c + 1] = s1;
                sQ[wm*128 + c]     = q0;  sQ[wm*128 + c + 1] = q1;
            }
        }
        __syncthreads();
        if (tid < 128){
            float s = sS[tid] + sS[128+tid] + sS[256+tid] + sS[384+tid];
            float q = sQ[tid] + sQ[128+tid] + sQ[256+tid] + sQ[384+tid];
            psum[blockIdx.x*256 + ncb + tid] = s;
            psq [blockIdx.x*256 + ncb + tid] = q;
        }
    }
}

// ---------------- fused gamma2 + softmax(K) + weighted output ----------------
#define VSTRIDE 132
__global__ __launch_bounds__(256, 2) void gemm_attn_kernel(
    const float* __restrict__ A,
    const __nv_bfloat16* __restrict__ Bh, const __nv_bfloat16* __restrict__ Bl,
    const float* __restrict__ bias, const float* __restrict__ bnp,
    const float* __restrict__ d2w, const float* __restrict__ d2b,
    float* __restrict__ out)
{
    extern __shared__ __align__(128) char dsm[];
    float* Vs = (float*)dsm;                     // reused after mainloop: 128 x VSTRIDE

    int tid = threadIdx.x, wid = tid >> 5, lane = tid & 31;
    int g = lane >> 2, t = lane & 3;
    int wm = wid & 3, wn = wid >> 2;
    const size_t rowbase = (size_t)blockIdx.x * 128;
    const int ncb = blockIdx.y * 128;

    float acc[2][8][4];
#pragma unroll
    for (int mt=0;mt<2;mt++)
#pragma unroll
        for (int nt=0;nt<8;nt++)
#pragma unroll
            for (int i=0;i<4;i++) acc[mt][nt][i]=0.f;

    gemm_mainloop<true>(A, Bh, Bl, bnp, dsm, rowbase, ncb, tid, wm, wn, acc);

    // bias -> logits
#pragma unroll
    for (int nt=0;nt<8;nt++){
        int col = ncb + wn*64 + nt*8 + 2*t;
        float b0 = bias[col], b1 = bias[col+1];
#pragma unroll
        for (int mt=0;mt<2;mt++){
            acc[mt][nt][0]+=b0; acc[mt][nt][1]+=b1;
            acc[mt][nt][2]+=b0; acc[mt][nt][3]+=b1;
        }
    }

    __syncthreads();   // tiles no longer needed; reuse as Vs

    // stage gathered v rows
    {
        int r = tid >> 1;
        int half = (tid & 1) * 64;
        size_t grow = rowbase + r;
        int gpt = (int)(grow >> 4);
        int b = gpt >> 12;
        int j = g_idx[grow];
        const float* vp = g_vf + ((size_t)(b*NP + j))*256 + ncb + half;
        float* dst = Vs + r*VSTRIDE + half;
#pragma unroll
        for (int i=0;i<16;i++)
            *(float4*)(dst + i*4) = *(const float4*)(vp + i*4);
    }

    // softmax over K — register + shfl only
#pragma unroll
    for (int mt=0;mt<2;mt++)
#pragma unroll
    for (int nt=0;nt<8;nt++){
        float a0=acc[mt][nt][0], a1=acc[mt][nt][1], a2=acc[mt][nt][2], a3=acc[mt][nt][3];
        float m0 = fmaxf(a0,a2), m1 = fmaxf(a1,a3);
#pragma unroll
        for (int mk=4; mk<=16; mk<<=1){
            m0 = fmaxf(m0, __shfl_xor_sync(0xffffffffu, m0, mk));
            m1 = fmaxf(m1, __shfl_xor_sync(0xffffffffu, m1, mk));
        }
        float e0=expf(a0-m0), e2=expf(a2-m0), e1=expf(a1-m1), e3=expf(a3-m1);
        float s0=e0+e2, s1=e1+e3;
#pragma unroll
        for (int mk=4; mk<=16; mk<<=1){
            s0 += __shfl_xor_sync(0xffffffffu, s0, mk);
            s1 += __shfl_xor_sync(0xffffffffu, s1, mk);
        }
        float i0=1.f/s0, i1=1.f/s1;
        acc[mt][nt][0]=e0*i0; acc[mt][nt][1]=e1*i1;
        acc[mt][nt][2]=e2*i0; acc[mt][nt][3]=e3*i1;
    }

    // u vectors for this thread's 2x2 k-rows
    float3 uv[2][2];
#pragma unroll
    for (int mt=0;mt<2;mt++)
#pragma unroll
    for (int kk=0;kk<2;kk++){
        size_t r = rowbase + wm*32 + mt*16 + g + kk*8;
        uv[mt][kk] = make_float3(g_u[r*3], g_u[r*3+1], g_u[r*3+2]);
    }

    __syncthreads();   // Vs ready

    // weighted output
#pragma unroll
    for (int nt=0;nt<8;nt++){
        int c0 = wn*64 + nt*8 + 2*t;
        int gc = ncb + c0;
        float w0a=d2w[gc],   w1a=d2w[256+gc],   w2a=d2w[512+gc],   ba=d2b[gc];
        float w0b=d2w[gc+1], w1b=d2w[257+gc],   w2b=d2w[513+gc],   bb=d2b[gc+1];
#pragma unroll
        for (int mt=0;mt<2;mt++){
            float o0=0.f, o1=0.f;
#pragma unroll
            for (int kk=0;kk<2;kk++){
                int r = wm*32 + mt*16 + g + kk*8;
                float2 v = *(const float2*)&Vs[r*VSTRIDE + c0];
                float3 u = uv[mt][kk];
                float pea = u.x*w0a + u.y*w1a + u.z*w2a + ba;
                float peb = u.x*w0b + u.y*w1b + u.z*w2b + bb;
                o0 += acc[mt][nt][kk*2+0] * (v.x + pea);
                o1 += acc[mt][nt][kk*2+1] * (v.y + peb);
            }
#pragma unroll
            for (int mk=4; mk<=16; mk<<=1){
                o0 += __shfl_xor_sync(0xffffffffu, o0, mk);
                o1 += __shfl_xor_sync(0xffffffffu, o1, mk);
            }
            if (g == 0){
                size_t pt = (rowbase >> 4) + 2*wm + mt;
                *(float2*)&out[pt*256 + gc] = make_float2(o0, o1);
            }
        }
    }
}

// ---------------- finalize per-channel BN over 256 channels ----------------
__global__ __launch_bounds__(256) void bnfin_kernel(const float* __restrict__ psum,
                                                    const float* __restrict__ psq, int P,
                                                    const float* __restrict__ g,
                                                    const float* __restrict__ beta,
                                                    float* __restrict__ outp)
{
    int c = threadIdx.x;
    double s=0.0,q=0.0;
    for (int i=0;i<P;i++){ s+=psum[i*NC+c]; q+=psq[i*NC+c]; }
    double m = s/(double)NROWS;
    double v = q/(double)NROWS - m*m;
    double sc = (double)g[c] / sqrt(v+1e-5);
    outp[c]    = (float)sc;
    outp[NC+c] = (float)((double)beta[c] - m*sc);
}

// ---------------- h producer ----------------
__global__ __launch_bounds__(256) void hprod_kernel(
    const float* __restrict__ xyz, const float* __restrict__ d1w, const float* __restrict__ d1b,
    const float* __restrict__ d2w, const float* __restrict__ d2b)
{
    __shared__ float su[NK*3];
    __shared__ int   sj[NK];
    int c = threadIdx.x;
    float d2c0 = d2w[c], d2c1 = d2w[256+c], d2c2 = d2w[512+c], d2bc = d2b[c];
    float s=0.f, q=0.f;
    for (int pp=0; pp<32; pp++){
        int pt = blockIdx.x*32 + pp;
        int b  = pt >> 12;
        if (c < NK){
            int k = c;
            int j = g_idx[pt*NK+k];
            sj[k]=j;
            float r0 = xyz[pt*3+0]-xyz[(b*NP+j)*3+0];
            float r1 = xyz[pt*3+1]-xyz[(b*NP+j)*3+1];
            float r2 = xyz[pt*3+2]-xyz[(b*NP+j)*3+2];
#pragma unroll
            for (int d=0;d<3;d++){
                float t  = r0*d1w[d] + r1*d1w[3+d] + r2*d1w[6+d] + d1b[d];
                float uu = fmaxf(0.f, fmaf(t, g_bnd[d], g_bnd[3+d]));
                su[k*3+d]=uu;
                g_u[(pt*NK+k)*3+d]=uu;
            }
        }
        __syncthreads();
        float qv = g_q[pt*NC + c];
#pragma unroll
        for (int k=0;k<NK;k++){
            int j = sj[k];
            float kv = g_kf[(b*NP+j)*NC + c];
            float pe = su[k*3]*d2c0 + su[k*3+1]*d2c1 + su[k*3+2]*d2c2 + d2bc;
            float h = qv - kv + pe;
            g_h[(size_t)(pt*NK+k)*NC + c] = h;
            s += h; q += h*h;
        }
        __syncthreads();
    }
    g_ps1[blockIdx.x*NC+c]=s;
    g_pq1[blockIdx.x*NC+c]=q;
}

// ---------------- host launcher ----------------
extern "C" void kernel_launch(void* const* d_in, const int* in_sizes, int n_in,
                              void* d_out, int out_size)
{
    const float* xyz  = (const float*)d_in[0];
    const float* feat = (const float*)d_in[1];
    const float* wq   = (const float*)d_in[2];  const float* bq  = (const float*)d_in[3];
    const float* wk   = (const float*)d_in[4];  const float* bk  = (const float*)d_in[5];
    const float* wv   = (const float*)d_in[6];  const float* bv  = (const float*)d_in[7];
    const float* d1w  = (const float*)d_in[8];  const float* d1b = (const float*)d_in[9];
    const float* bndg = (const float*)d_in[10]; const float* bndb= (const float*)d_in[11];
    const float* d2w  = (const float*)d_in[12]; const float* d2b = (const float*)d_in[13];
    const float* g1g  = (const float*)d_in[14]; const float* g1bt= (const float*)d_in[15];
    const float* g1w  = (const float*)d_in[16]; const float* g1b = (const float*)d_in[17];
    const float* g2g  = (const float*)d_in[18]; const float* g2bt= (const float*)d_in[19];
    const float* g2w  = (const float*)d_in[20]; const float* g2b = (const float*)d_in[21];
    float* out = (float*)d_out;

    float *p_q,*p_kf,*p_vf,*p_h,*p_h2,*p_bn1,*p_bn2,*p_ps1,*p_pq1,*p_ps2,*p_pq2;
    __nv_bfloat16 *p_bh1,*p_bl1,*p_bh2,*p_bl2,*p_bhq,*p_blq,*p_bhk,*p_blk,*p_bhv,*p_blv;
    cudaGetSymbolAddress((void**)&p_q,  g_q);
    cudaGetSymbolAddress((void**)&p_kf, g_kf);
    cudaGetSymbolAddress((void**)&p_vf, g_vf);
    cudaGetSymbolAddress((void**)&p_h,  g_h);
    cudaGetSymbolAddress((void**)&p_h2, g_h2);
    cudaGetSymbolAddress((void**)&p_bn1,g_bn1);
    cudaGetSymbolAddress((void**)&p_bn2,g_bn2);
    cudaGetSymbolAddress((void**)&p_ps1,g_ps1);
    cudaGetSymbolAddress((void**)&p_pq1,g_pq1);
    cudaGetSymbolAddress((void**)&p_ps2,g_ps2);
    cudaGetSymbolAddress((void**)&p_pq2,g_pq2);
    cudaGetSymbolAddress((void**)&p_bh1,g_bh1);
    cudaGetSymbolAddress((void**)&p_bl1,g_bl1);
    cudaGetSymbolAddress((void**)&p_bh2,g_bh2);
    cudaGetSymbolAddress((void**)&p_bl2,g_bl2);
    cudaGetSymbolAddress((void**)&p_bhq,g_bhq);
    cudaGetSymbolAddress((void**)&p_blq,g_blq);
    cudaGetSymbolAddress((void**)&p_bhk,g_bhk);
    cudaGetSymbolAddress((void**)&p_blk,g_blk);
    cudaGetSymbolAddress((void**)&p_bhv,g_bhv);
    cudaGetSymbolAddress((void**)&p_blv,g_blv);

    cudaFuncSetAttribute(gemm_mma_kernel<false,false>,
                         cudaFuncAttributeMaxDynamicSharedMemorySize, SM_TOTAL);
    cudaFuncSetAttribute(gemm_mma_kernel<true,true>,
                         cudaFuncAttributeMaxDynamicSharedMemorySize, SM_TOTAL);
    cudaFuncSetAttribute(gemm_attn_kernel,
                         cudaFuncAttributeMaxDynamicSharedMemorySize, SM_TOTAL);

    // Launch order: slot #4 (ncu capture) = knn_kernel this round.
    bprep5_kernel<<<dim3(NC,5),NC>>>(g1w, g2w, wq, wk, wv);
    gemm_mma_kernel<false,false><<<dim3(NPTS/128,2),256,SM_TOTAL>>>(feat, p_bhq, p_blq, bq, nullptr, p_q,  nullptr, nullptr);
    gemm_mma_kernel<false,false><<<dim3(NPTS/128,2),256,SM_TOTAL>>>(feat, p_bhk, p_blk, bk, nullptr, p_kf, nullptr, nullptr);
    knn_kernel<<<dim3(NP/16, NB), 512>>>(xyz);
    gemm_mma_kernel<false,false><<<dim3(NPTS/128,2),256,SM_TOTAL>>>(feat, p_bhv, p_blv, bv, nullptr, p_vf, nullptr, nullptr);
    dstat_kernel<<<512,256>>>(xyz, d1w, d1b);
    dfin_kernel<<<1,32>>>(bndg, bndb);
    hprod_kernel<<<512,256>>>(xyz, d1w, d1b, d2w, d2b);
    bnfin_kernel<<<1,256>>>(p_ps1, p_pq1, 512, g1g, g1bt, p_bn1);
    gemm_mma_kernel<true,true><<<dim3(NROWS/128,2),256,SM_TOTAL>>>(p_h, p_bh1, p_bl1, g1b, p_bn1, p_h2, p_ps2, p_pq2);
    bnfin_kernel<<<1,256>>>(p_ps2, p_pq2, 2048, g2g, g2bt, p_bn2);
    gemm_attn_kernel<<<dim3(NROWS/128,2),256,SM_TOTAL>>>(
        p_h2, p_bh2, p_bl2, g2b, p_bn2, d2w, d2b, out);
}

// round 15
// speedup vs baseline: 1.6451x; 1.6451x over previous
#include <cuda_runtime.h>
#include <cuda_bf16.h>
#include <math.h>
#include <float.h>

#define NB 4
#define NP 4096
#define NC 256
#define NK 16
#define NPTS (NB*NP)      /* 16384 */
#define NROWS (NPTS*NK)   /* 262144 */

// ---------------- scratch (device globals; no allocation) ----------------
__device__ float g_q [NPTS*NC];
__device__ float g_kf[NPTS*NC];
__device__ float g_vf[NPTS*NC];
__device__ int   g_idx[NROWS];
__device__ float g_u [NROWS*3];
__device__ float g_h [NROWS*NC];
__device__ float g_h2[NROWS*NC];
__device__ float g_bnd[6];
__device__ float g_partd[512*6];
__device__ float g_ps1[512*NC];
__device__ float g_pq1[512*NC];
__device__ float g_ps2[2048*NC];
__device__ float g_pq2[2048*NC];
__device__ float g_bn1[2*NC];
__device__ float g_bn2[2*NC];
__device__ __nv_bfloat16 g_bh1[NC*NC], g_bl1[NC*NC];
__device__ __nv_bfloat16 g_bh2[NC*NC], g_bl2[NC*NC];
__device__ __nv_bfloat16 g_bhq[NC*NC], g_blq[NC*NC];
__device__ __nv_bfloat16 g_bhk[NC*NC], g_blk[NC*NC];
__device__ __nv_bfloat16 g_bhv[NC*NC], g_blv[NC*NC];

// ---------------- exact-rounding helpers for KNN ----------------
__device__ __forceinline__ float sq3_exact(float x, float y, float z){
    return __fadd_rn(__fadd_rn(__fmul_rn(x,x), __fmul_rn(y,y)), __fmul_rn(z,z));
}
__device__ __forceinline__ float dist_exact(float qx,float qy,float qz,float qw,
                                            float px,float py,float pz,float pw){
    float dot = __fmaf_rn(qz, pz, __fmaf_rn(qy, py, __fmul_rn(qx, px)));
    return __fsub_rn(__fadd_rn(qw, pw), __fmul_rn(2.0f, dot));
}

// ---------------- KNN: 8 queries/block (one per warp), 3 blocks/SM ----------------
__global__ __launch_bounds__(256, 3) void knn_kernel(const float* __restrict__ xyz)
{
    constexpr int CH = 2048;
    __shared__ float4 pts[CH];
    int b = blockIdx.y;
    const float* xb = xyz + b*NP*3;
    int warp = threadIdx.x >> 5, lane = threadIdx.x & 31;
    int n = blockIdx.x*8 + warp;
    float qx = xb[n*3+0], qy = xb[n*3+1], qz = xb[n*3+2];
    float qw = sq3_exact(qx, qy, qz);
    float dl[NK]; int il[NK];
#pragma unroll
    for (int j=0;j<NK;j++){ dl[j]=FLT_MAX; il[j]=0x7fffffff; }

    for (int c0=0;c0<NP;c0+=CH){
        __syncthreads();
        for (int i=threadIdx.x;i<CH;i+=256){
            int m=c0+i;
            float x=xb[m*3],y=xb[m*3+1],z=xb[m*3+2];
            pts[i]=make_float4(x,y,z, sq3_exact(x,y,z));
        }
        __syncthreads();
        for (int i=lane;i<CH;i+=64){
            float4 p0=pts[i];
            float4 p1=pts[i+32];
            int m0=c0+i, m1=c0+i+32;
            float d0 = dist_exact(qx,qy,qz,qw, p0.x,p0.y,p0.z,p0.w);
            float d1 = dist_exact(qx,qy,qz,qw, p1.x,p1.y,p1.z,p1.w);
            if (d0 < dl[NK-1] || (d0==dl[NK-1] && m0<il[NK-1])){
                dl[NK-1]=d0; il[NK-1]=m0;
#pragma unroll
                for (int j=NK-1;j>0;j--){
                    bool sw = dl[j]<dl[j-1] || (dl[j]==dl[j-1] && il[j]<il[j-1]);
                    float t0 = sw? dl[j-1]:dl[j];
                    float t1 = sw? dl[j]:dl[j-1];
                    int   i0 = sw? il[j-1]:il[j];
                    int   i1 = sw? il[j]:il[j-1];
                    dl[j]=t0; dl[j-1]=t1; il[j]=i0; il[j-1]=i1;
                }
            }
            if (d1 < dl[NK-1] || (d1==dl[NK-1] && m1<il[NK-1])){
                dl[NK-1]=d1; il[NK-1]=m1;
#pragma unroll
                for (int j=NK-1;j>0;j--){
                    bool sw = dl[j]<dl[j-1] || (dl[j]==dl[j-1] && il[j]<il[j-1]);
                    float t0 = sw? dl[j-1]:dl[j];
                    float t1 = sw? dl[j]:dl[j-1];
                    int   i0 = sw? il[j-1]:il[j];
                    int   i1 = sw? il[j]:il[j-1];
                    dl[j]=t0; dl[j-1]=t1; il[j]=i0; il[j-1]=i1;
                }
            }
        }
    }
    for (int r=0;r<NK;r++){
        float cd = dl[0]; int ci = il[0];
        float rd = cd;    int ri = ci;
#pragma unroll
        for (int off=16; off>0; off>>=1){
            float od = __shfl_down_sync(0xffffffffu, rd, off);
            int   oi = __shfl_down_sync(0xffffffffu, ri, off);
            if (od<rd || (od==rd && oi<ri)){ rd=od; ri=oi; }
        }
        rd = __shfl_sync(0xffffffffu, rd, 0);
        ri = __shfl_sync(0xffffffffu, ri, 0);
        if (lane==0) g_idx[(b*NP+n)*NK + r] = ri;
        if (cd==rd && ci==ri){
#pragma unroll
            for (int j=0;j<NK-1;j++){ dl[j]=dl[j+1]; il[j]=il[j+1]; }
            dl[NK-1]=FLT_MAX; il[NK-1]=0x7fffffff;
        }
    }
}

// ---------------- d-path BN stats ----------------
__global__ __launch_bounds__(256) void dstat_kernel(const float* __restrict__ xyz,
                                                    const float* __restrict__ d1w,
                                                    const float* __restrict__ d1b)
{
    float s[3]={0.f,0.f,0.f}, sq[3]={0.f,0.f,0.f};
    int stride = gridDim.x*blockDim.x;
    for (int it = blockIdx.x*blockDim.x+threadIdx.x; it < NROWS; it += stride){
        int pt = it >> 4;
        int b  = pt >> 12;
        int j  = g_idx[it];
        float r0 = xyz[pt*3+0] - xyz[(b*NP+j)*3+0];
        float r1 = xyz[pt*3+1] - xyz[(b*NP+j)*3+1];
        float r2 = xyz[pt*3+2] - xyz[(b*NP+j)*3+2];
#pragma unroll
        for (int d=0;d<3;d++){
            float t = r0*d1w[d] + r1*d1w[3+d] + r2*d1w[6+d] + d1b[d];
            s[d]+=t; sq[d]+=t*t;
        }
    }
    __shared__ float red[256];
    for (int q=0;q<6;q++){
        red[threadIdx.x] = (q<3)? s[q] : sq[q-3];
        __syncthreads();
        for (int st=128; st; st>>=1){
            if (threadIdx.x<st) red[threadIdx.x]+=red[threadIdx.x+st];
            __syncthreads();
        }
        if (threadIdx.x==0) g_partd[blockIdx.x*6+q]=red[0];
        __syncthreads();
    }
}

__global__ void dfin_kernel(const float* __restrict__ g, const float* __restrict__ beta)
{
    int d = threadIdx.x;
    if (d>=3) return;
    double s=0.0,q=0.0;
    for (int i=0;i<512;i++){ s+=g_partd[i*6+d]; q+=g_partd[i*6+3+d]; }
    double m = s/(double)NROWS;
    double v = q/(double)NROWS - m*m;
    double sc = (double)g[d] / sqrt(v+1e-5);
    g_bnd[d]   = (float)sc;
    g_bnd[3+d] = (float)((double)beta[d] - m*sc);
}

// ---------------- weight prep (all 5 matrices, one launch) ----------------
__global__ void bprep5_kernel(const float* __restrict__ g1w, const float* __restrict__ g2w,
                              const float* __restrict__ wq,  const float* __restrict__ wk,
                              const float* __restrict__ wv)
{
    int k = blockIdx.x, n = threadIdx.x;
    const float* W; __nv_bfloat16 *H, *L;
    switch (blockIdx.y){
        case 0: W=g1w; H=g_bh1; L=g_bl1; break;
        case 1: W=g2w; H=g_bh2; L=g_bl2; break;
        case 2: W=wq;  H=g_bhq; L=g_blq; break;
        case 3: W=wk;  H=g_bhk; L=g_blk; break;
        default:W=wv;  H=g_bhv; L=g_blv; break;
    }
    float w = W[k*NC+n];
    __nv_bfloat16 h = __float2bfloat16_rn(w);
    H[n*NC+k] = h;
    L[n*NC+k] = __float2bfloat16_rn(w - __bfloat162float(h));
}

// ---------------- HMMA helpers ----------------
__device__ __forceinline__ void mma_bf16(float* c, const unsigned* a, const unsigned* b){
    asm volatile(
      "mma.sync.aligned.m16n8k16.row.col.f32.bf16.bf16.f32 "
      "{%0,%1,%2,%3}, {%4,%5,%6,%7}, {%8,%9}, {%0,%1,%2,%3};"
      : "+f"(c[0]),"+f"(c[1]),"+f"(c[2]),"+f"(c[3])
      : "r"(a[0]),"r"(a[1]),"r"(a[2]),"r"(a[3]), "r"(b[0]),"r"(b[1]));
}
__device__ __forceinline__ void ldmx4(unsigned* r, unsigned addr){
    asm volatile("ldmatrix.sync.aligned.m8n8.x4.shared.b16 {%0,%1,%2,%3}, [%4];"
                 : "=r"(r[0]),"=r"(r[1]),"=r"(r[2]),"=r"(r[3]) : "r"(addr));
}
__device__ __forceinline__ void cpa16(unsigned dst, const void* src){
    asm volatile("cp.async.cg.shared.global [%0], [%1], 16;" :: "r"(dst), "l"(src));
}
#define CPA_COMMIT asm volatile("cp.async.commit_group;" ::: "memory")
#define CPA_WAIT0  asm volatile("cp.async.wait_group 0;" ::: "memory")

#define KC 32           /* K-chunk */
#define RSTRIDE 40      /* bf16 tile row stride in halves: 80B, ldmatrix conflict-free */
#define ATILE 10240     /* bytes per 128xKC bf16 tile */
#define AFSTRIDE 36     /* fp32 A staging row stride in words */
// dynamic smem layout
#define SM_ASH 0
#define SM_ASL ATILE
#define SM_BH(buf) (2*ATILE + (buf)*2*ATILE)
#define SM_BL(buf) (3*ATILE + (buf)*2*ATILE)
#define SM_AF(buf) (6*ATILE + (buf)*(128*AFSTRIDE*4))
#define SM_TOTAL (6*ATILE + 2*(128*AFSTRIDE*4))   /* 98304 */

// Shared mainloop (R12 version): cp.async double-buffered pipeline, 3 sequential
// HMMA passes via ldmatrix (no extra register pressure).
template<bool BNRELU>
__device__ __forceinline__ void gemm_mainloop(
    const float* __restrict__ A, const __nv_bfloat16* __restrict__ Bh,
    const __nv_bfloat16* __restrict__ Bl, const float* __restrict__ bnp,
    char* dsm, size_t rowbase, int ncb, int tid, int wm, int wn,
    float acc[2][8][4])
{
    int lane = tid & 31;
    int lr = tid >> 1;
    int cg = (tid & 1) * 16;
    int q3 = lane >> 3, rl = lane & 7;
    unsigned sb = (unsigned)__cvta_generic_to_shared(dsm);
    unsigned aoffA = (unsigned)(((wm*32 + (q3&1)*8 + rl) * RSTRIDE + (q3>>1)*8) * 2);
    unsigned aoffB = (unsigned)(((wn*64 + (q3>>1)*8 + rl) * RSTRIDE + (q3&1)*8) * 2);

    const float*         asrc0 = A  + (rowbase + lr)*256 + cg;
    const __nv_bfloat16* bhs0  = Bh + (size_t)(ncb + lr)*256 + cg;
    const __nv_bfloat16* bls0  = Bl + (size_t)(ncb + lr)*256 + cg;
    unsigned adst_r = (unsigned)((lr*AFSTRIDE + cg)*4);
    unsigned bdst_r = (unsigned)((lr*RSTRIDE  + cg)*2);

    // prologue: chunk 0 -> buffers 0
    {
        unsigned ad = sb + SM_AF(0) + adst_r;
        cpa16(ad,    asrc0);     cpa16(ad+16, asrc0+4);
        cpa16(ad+32, asrc0+8);   cpa16(ad+48, asrc0+12);
        unsigned bh = sb + SM_BH(0) + bdst_r;
        unsigned bl = sb + SM_BL(0) + bdst_r;
        cpa16(bh, bhs0); cpa16(bh+16, bhs0+8);
        cpa16(bl, bls0); cpa16(bl+16, bls0+8);
        CPA_COMMIT;
    }

    for (int ic = 0; ic < 8; ic++){
        int buf = ic & 1;
        CPA_WAIT0;
        __syncthreads();

        if (ic < 7){
            int kc1 = (ic+1)*KC;
            unsigned ad = sb + SM_AF(buf^1) + adst_r;
            const float* as = asrc0 + kc1;
            cpa16(ad,    as);    cpa16(ad+16, as+4);
            cpa16(ad+32, as+8);  cpa16(ad+48, as+12);
            unsigned bh = sb + SM_BH(buf^1) + bdst_r;
            unsigned bl = sb + SM_BL(buf^1) + bdst_r;
            cpa16(bh, bhs0 + kc1); cpa16(bh+16, bhs0 + kc1 + 8);
            cpa16(bl, bls0 + kc1); cpa16(bl+16, bls0 + kc1 + 8);
            CPA_COMMIT;
        }

        // convert A chunk ic: smem fp32 -> bnrelu -> bf16 hi/lo tiles
        {
            int kc0 = ic*KC;
            const float* af = (const float*)(dsm + SM_AF(buf)) + lr*AFSTRIDE + cg;
            float v[16];
            *(float4*)(v)    = *(const float4*)(af);
            *(float4*)(v+4)  = *(const float4*)(af+4);
            *(float4*)(v+8)  = *(const float4*)(af+8);
            *(float4*)(v+12) = *(const float4*)(af+12);
            unsigned hh[8], ll[8];
#pragma unroll
            for (int p=0;p<8;p++){
                float a0 = v[p*2], a1 = v[p*2+1];
                if (BNRELU){
                    int c = kc0 + cg + p*2;
                    a0 = fmaxf(0.f, fmaf(a0, bnp[c],   bnp[256+c]));
                    a1 = fmaxf(0.f, fmaf(a1, bnp[c+1], bnp[257+c]));
                }
                __nv_bfloat16 h0 = __float2bfloat16_rn(a0);
                __nv_bfloat16 h1 = __float2bfloat16_rn(a1);
                __nv_bfloat16 l0 = __float2bfloat16_rn(a0 - __bfloat162float(h0));
                __nv_bfloat16 l1 = __float2bfloat16_rn(a1 - __bfloat162float(h1));
                hh[p] = (unsigned)__bfloat16_as_ushort(h0) | ((unsigned)__bfloat16_as_ushort(h1)<<16);
                ll[p] = (unsigned)__bfloat16_as_ushort(l0) | ((unsigned)__bfloat16_as_ushort(l1)<<16);
            }
            unsigned short (*AsH)[RSTRIDE] = (unsigned short(*)[RSTRIDE])(dsm + SM_ASH);
            unsigned short (*AsL)[RSTRIDE] = (unsigned short(*)[RSTRIDE])(dsm + SM_ASL);
            *(uint4*)&AsH[lr][cg]   = make_uint4(hh[0],hh[1],hh[2],hh[3]);
            *(uint4*)&AsH[lr][cg+8] = make_uint4(hh[4],hh[5],hh[6],hh[7]);
            *(uint4*)&AsL[lr][cg]   = make_uint4(ll[0],ll[1],ll[2],ll[3]);
            *(uint4*)&AsL[lr][cg+8] = make_uint4(ll[4],ll[5],ll[6],ll[7]);
        }
        __syncthreads();

        unsigned aASH = sb + SM_ASH, aASL = sb + SM_ASL;
        unsigned aBH  = sb + SM_BH(buf), aBL = sb + SM_BL(buf);
#pragma unroll
        for (int p=0;p<3;p++){
            unsigned Abase = (p==2)? aASL : aASH;
            unsigned Bbase = (p==1)? aBL  : aBH;
#pragma unroll
            for (int ks=0; ks<KC; ks+=16){
                unsigned af[2][4];
#pragma unroll
                for (int mt=0;mt<2;mt++)
                    ldmx4(af[mt], Abase + aoffA + (unsigned)((mt*16*RSTRIDE + ks)*2));
#pragma unroll
                for (int ntp=0;ntp<4;ntp++){
                    unsigned bb[4];
                    ldmx4(bb, Bbase + aoffB + (unsigned)((ntp*16*RSTRIDE + ks)*2));
                    mma_bf16(acc[0][2*ntp],   af[0], bb);
                    mma_bf16(acc[1][2*ntp],   af[1], bb);
                    mma_bf16(acc[0][2*ntp+1], af[0], bb+2);
                    mma_bf16(acc[1][2*ntp+1], af[1], bb+2);
                }
            }
        }
    }
}

// ---------------- GEMM (qkv / gamma1): store C, optional BN+fused stats ----------------
template<bool BNRELU, bool STATS>
__global__ __launch_bounds__(256, 2) void gemm_mma_kernel(
    const float* __restrict__ A,
    const __nv_bfloat16* __restrict__ Bh, const __nv_bfloat16* __restrict__ Bl,
    const float* __restrict__ bias, const float* __restrict__ bnp,
    float* __restrict__ C, float* __restrict__ psum, float* __restrict__ psq)
{
    extern __shared__ __align__(128) char dsm[];

    int tid = threadIdx.x, wid = tid >> 5, lane = tid & 31;
    int g = lane >> 2, t = lane & 3;
    int wm = wid & 3, wn = wid >> 2;
    const size_t rowbase = (size_t)blockIdx.x * 128;
    const int ncb = blockIdx.y * 128;

    float acc[2][8][4];
#pragma unroll
    for (int mt=0;mt<2;mt++)
#pragma unroll
        for (int nt=0;nt<8;nt++)
#pragma unroll
            for (int i=0;i<4;i++) acc[mt][nt][i]=0.f;

    gemm_mainloop<BNRELU>(A, Bh, Bl, bnp, dsm, rowbase, ncb, tid, wm, wn, acc);

#pragma unroll
    for (int nt=0;nt<8;nt++){
        int col = ncb + wn*64 + nt*8 + 2*t;
        float b0 = bias[col], b1 = bias[col+1];
#pragma unroll
        for (int mt=0;mt<2;mt++){
            acc[mt][nt][0]+=b0; acc[mt][nt][1]+=b1;
            acc[mt][nt][2]+=b0; acc[mt][nt][3]+=b1;
        }
    }
#pragma unroll
    for (int nt=0;nt<8;nt++){
        int col = ncb + wn*64 + nt*8 + 2*t;
#pragma unroll
        for (int mt=0;mt<2;mt++){
            size_t row = rowbase + wm*32 + mt*16 + g;
            *(float2*)&C[row*256 + col]     = make_float2(acc[mt][nt][0], acc[mt][nt][1]);
            *(float2*)&C[(row+8)*256 + col] = make_float2(acc[mt][nt][2], acc[mt][nt][3]);
        }
    }

    if (STATS){
        __syncthreads();
        float* sS = (float*)dsm;              // [4][128]
        float* sQ = sS + 512;
#pragma unroll
        for (int nt=0;nt<8;nt++){
            float s0=0.f,q0=0.f,s1=0.f,q1=0.f;
#pragma unroll
            for (int mt=0;mt<2;mt++){
                float v0=acc[mt][nt][0], v2=acc[mt][nt][2];
                float v1=acc[mt][nt][1], v3=acc[mt][nt][3];
                s0 += v0+v2;  q0 += v0*v0+v2*v2;
                s1 += v1+v3;  q1 += v1*v1+v3*v3;
            }
#pragma unroll
            for (int off=16; off>=4; off>>=1){
                s0 += __shfl_down_sync(0xffffffffu, s0, off);
                q0 += __shfl_down_sync(0xffffffffu, q0, off);
                s1 += __shfl_down_sync(0xffffffffu, s1, off);
                q1 += __shfl_down_sync(0xffffffffu, q1, off);
            }
            if (lane < 4){
                int c = wn*64 + nt*8 + 2*lane;
                sS[wm*128 + c]     = s0;  sS[wm*128 + c + 1] = s1;
                sQ[wm*128 + c]     = q0;  sQ[wm*128 + c + 1] = q1;
            }
        }
        __syncthreads();
        if (tid < 128){
            float s = sS[tid] + sS[128+tid] + sS[256+tid] + sS[384+tid];
            float q = sQ[tid] + sQ[128+tid] + sQ[256+tid] + sQ[384+tid];
            psum[blockIdx.x*256 + ncb + tid] = s;
            psq [blockIdx.x*256 + ncb + tid] = q;
        }
    }
}

// ---------------- fused gamma2 + softmax(K) + weighted output ----------------
#define VSTRIDE 132
__global__ __launch_bounds__(256, 2) void gemm_attn_kernel(
    const float* __restrict__ A,
    const __nv_bfloat16* __restrict__ Bh, const __nv_bfloat16* __restrict__ Bl,
    const float* __restrict__ bias, const float* __restrict__ bnp,
    const float* __restrict__ d2w, const float* __restrict__ d2b,
    float* __restrict__ out)
{
    extern __shared__ __align__(128) char dsm[];
    float* Vs = (float*)dsm;                     // reused after mainloop: 128 x VSTRIDE

    int tid = threadIdx.x, wid = tid >> 5, lane = tid & 31;
    int g = lane >> 2, t = lane & 3;
    int wm = wid & 3, wn = wid >> 2;
    const size_t rowbase = (size_t)blockIdx.x * 128;
    const int ncb = blockIdx.y * 128;

    float acc[2][8][4];
#pragma unroll
    for (int mt=0;mt<2;mt++)
#pragma unroll
        for (int nt=0;nt<8;nt++)
#pragma unroll
            for (int i=0;i<4;i++) acc[mt][nt][i]=0.f;

    gemm_mainloop<true>(A, Bh, Bl, bnp, dsm, rowbase, ncb, tid, wm, wn, acc);

    // bias -> logits
#pragma unroll
    for (int nt=0;nt<8;nt++){
        int col = ncb + wn*64 + nt*8 + 2*t;
        float b0 = bias[col], b1 = bias[col+1];
#pragma unroll
        for (int mt=0;mt<2;mt++){
            acc[mt][nt][0]+=b0; acc[mt][nt][1]+=b1;
            acc[mt][nt][2]+=b0; acc[mt][nt][3]+=b1;
        }
    }

    __syncthreads();   // tiles no longer needed; reuse as Vs

    // stage gathered v rows
    {
        int r = tid >> 1;
        int half = (tid & 1) * 64;
        size_t grow = rowbase + r;
        int gpt = (int)(grow >> 4);
        int b = gpt >> 12;
        int j = g_idx[grow];
        const float* vp = g_vf + ((size_t)(b*NP + j))*256 + ncb + half;
        float* dst = Vs + r*VSTRIDE + half;
#pragma unroll
        for (int i=0;i<16;i++)
            *(float4*)(dst + i*4) = *(const float4*)(vp + i*4);
    }

    // softmax over K — register + shfl only
#pragma unroll
    for (int mt=0;mt<2;mt++)
#pragma unroll
    for (int nt=0;nt<8;nt++){
        float a0=acc[mt][nt][0], a1=acc[mt][nt][1], a2=acc[mt][nt][2], a3=acc[mt][nt][3];
        float m0 = fmaxf(a0,a2), m1 = fmaxf(a1,a3);
#pragma unroll
        for (int mk=4; mk<=16; mk<<=1){
            m0 = fmaxf(m0, __shfl_xor_sync(0xffffffffu, m0, mk));
            m1 = fmaxf(m1, __shfl_xor_sync(0xffffffffu, m1, mk));
        }
        float e0=expf(a0-m0), e2=expf(a2-m0), e1=expf(a1-m1), e3=expf(a3-m1);
        float s0=e0+e2, s1=e1+e3;
#pragma unroll
        for (int mk=4; mk<=16; mk<<=1){
            s0 += __shfl_xor_sync(0xffffffffu, s0, mk);
            s1 += __shfl_xor_sync(0xffffffffu, s1, mk);
        }
        float i0=1.f/s0, i1=1.f/s1;
        acc[mt][nt][0]=e0*i0; acc[mt][nt][1]=e1*i1;
        acc[mt][nt][2]=e2*i0; acc[mt][nt][3]=e3*i1;
    }

    // u vectors for this thread's 2x2 k-rows
    float3 uv[2][2];
#pragma unroll
    for (int mt=0;mt<2;mt++)
#pragma unroll
    for (int kk=0;kk<2;kk++){
        size_t r = rowbase + wm*32 + mt*16 + g + kk*8;
        uv[mt][kk] = make_float3(g_u[r*3], g_u[r*3+1], g_u[r*3+2]);
    }

    __syncthreads();   // Vs ready

    // weighted output
#pragma unroll
    for (int nt=0;nt<8;nt++){
        int c0 = wn*64 + nt*8 + 2*t;
        int gc = ncb + c0;
        float w0a=d2w[gc],   w1a=d2w[256+gc],   w2a=d2w[512+gc],   ba=d2b[gc];
        float w0b=d2w[gc+1], w1b=d2w[257+gc],   w2b=d2w[513+gc],   bb=d2b[gc+1];
#pragma unroll
        for (int mt=0;mt<2;mt++){
            float o0=0.f, o1=0.f;
#pragma unroll
            for (int kk=0;kk<2;kk++){
                int r = wm*32 + mt*16 + g + kk*8;
                float2 v = *(const float2*)&Vs[r*VSTRIDE + c0];
                float3 u = uv[mt][kk];
                float pea = u.x*w0a + u.y*w1a + u.z*w2a + ba;
                float peb = u.x*w0b + u.y*w1b + u.z*w2b + bb;
                o0 += acc[mt][nt][kk*2+0] * (v.x + pea);
                o1 += acc[mt][nt][kk*2+1] * (v.y + peb);
            }
#pragma unroll
            for (int mk=4; mk<=16; mk<<=1){
                o0 += __shfl_xor_sync(0xffffffffu, o0, mk);
                o1 += __shfl_xor_sync(0xffffffffu, o1, mk);
            }
            if (g == 0){
                size_t pt = (rowbase >> 4) + 2*wm + mt;
                *(float2*)&out[pt*256 + gc] = make_float2(o0, o1);
            }
        }
    }
}

// ---------------- finalize per-channel BN over 256 channels ----------------
__global__ __launch_bounds__(256) void bnfin_kernel(const float* __restrict__ psum,
                                                    const float* __restrict__ psq, int P,
                                                    const float* __restrict__ g,
                                                    const float* __restrict__ beta,
                                                    float* __restrict__ outp)
{
    int c = threadIdx.x;
    double s=0.0,q=0.0;
    for (int i=0;i<P;i++){ s+=psum[i*NC+c]; q+=psq[i*NC+c]; }
    double m = s/(double)NROWS;
    double v = q/(double)NROWS - m*m;
    double sc = (double)g[c] / sqrt(v+1e-5);
    outp[c]    = (float)sc;
    outp[NC+c] = (float)((double)beta[c] - m*sc);
}

// ---------------- h producer ----------------
__global__ __launch_bounds__(256) void hprod_kernel(
    const float* __restrict__ xyz, const float* __restrict__ d1w, const float* __restrict__ d1b,
    const float* __restrict__ d2w, const float* __restrict__ d2b)
{
    __shared__ float su[NK*3];
    __shared__ int   sj[NK];
    int c = threadIdx.x;
    float d2c0 = d2w[c], d2c1 = d2w[256+c], d2c2 = d2w[512+c], d2bc = d2b[c];
    float s=0.f, q=0.f;
    for (int pp=0; pp<32; pp++){
        int pt = blockIdx.x*32 + pp;
        int b  = pt >> 12;
        if (c < NK){
            int k = c;
            int j = g_idx[pt*NK+k];
            sj[k]=j;
            float r0 = xyz[pt*3+0]-xyz[(b*NP+j)*3+0];
            float r1 = xyz[pt*3+1]-xyz[(b*NP+j)*3+1];
            float r2 = xyz[pt*3+2]-xyz[(b*NP+j)*3+2];
#pragma unroll
            for (int d=0;d<3;d++){
                float t  = r0*d1w[d] + r1*d1w[3+d] + r2*d1w[6+d] + d1b[d];
                float uu = fmaxf(0.f, fmaf(t, g_bnd[d], g_bnd[3+d]));
                su[k*3+d]=uu;
                g_u[(pt*NK+k)*3+d]=uu;
            }
        }
        __syncthreads();
        float qv = g_q[pt*NC + c];
#pragma unroll
        for (int k=0;k<NK;k++){
            int j = sj[k];
            float kv = g_kf[(b*NP+j)*NC + c];
            float pe = su[k*3]*d2c0 + su[k*3+1]*d2c1 + su[k*3+2]*d2c2 + d2bc;
            float h = qv - kv + pe;
            g_h[(size_t)(pt*NK+k)*NC + c] = h;
            s += h; q += h*h;
        }
        __syncthreads();
    }
    g_ps1[blockIdx.x*NC+c]=s;
    g_pq1[blockIdx.x*NC+c]=q;
}

// ---------------- host launcher ----------------
extern "C" void kernel_launch(void* const* d_in, const int* in_sizes, int n_in,
                              void* d_out, int out_size)
{
    const float* xyz  = (const float*)d_in[0];
    const float* feat = (const float*)d_in[1];
    const float* wq   = (const float*)d_in[2];  const float* bq  = (const float*)d_in[3];
    const float* wk   = (const float*)d_in[4];  const float* bk  = (const float*)d_in[5];
    const float* wv   = (const float*)d_in[6];  const float* bv  = (const float*)d_in[7];
    const float* d1w  = (const float*)d_in[8];  const float* d1b = (const float*)d_in[9];
    const float* bndg = (const float*)d_in[10]; const float* bndb= (const float*)d_in[11];
    const float* d2w  = (const float*)d_in[12]; const float* d2b = (const float*)d_in[13];
    const float* g1g  = (const float*)d_in[14]; const float* g1bt= (const float*)d_in[15];
    const float* g1w  = (const float*)d_in[16]; const float* g1b = (const float*)d_in[17];
    const float* g2g  = (const float*)d_in[18]; const float* g2bt= (const float*)d_in[19];
    const float* g2w  = (const float*)d_in[20]; const float* g2b = (const float*)d_in[21];
    float* out = (float*)d_out;

    float *p_q,*p_kf,*p_vf,*p_h,*p_h2,*p_bn1,*p_bn2,*p_ps1,*p_pq1,*p_ps2,*p_pq2;
    __nv_bfloat16 *p_bh1,*p_bl1,*p_bh2,*p_bl2,*p_bhq,*p_blq,*p_bhk,*p_blk,*p_bhv,*p_blv;
    cudaGetSymbolAddress((void**)&p_q,  g_q);
    cudaGetSymbolAddress((void**)&p_kf, g_kf);
    cudaGetSymbolAddress((void**)&p_vf, g_vf);
    cudaGetSymbolAddress((void**)&p_h,  g_h);
    cudaGetSymbolAddress((void**)&p_h2, g_h2);
    cudaGetSymbolAddress((void**)&p_bn1,g_bn1);
    cudaGetSymbolAddress((void**)&p_bn2,g_bn2);
    cudaGetSymbolAddress((void**)&p_ps1,g_ps1);
    cudaGetSymbolAddress((void**)&p_pq1,g_pq1);
    cudaGetSymbolAddress((void**)&p_ps2,g_ps2);
    cudaGetSymbolAddress((void**)&p_pq2,g_pq2);
    cudaGetSymbolAddress((void**)&p_bh1,g_bh1);
    cudaGetSymbolAddress((void**)&p_bl1,g_bl1);
    cudaGetSymbolAddress((void**)&p_bh2,g_bh2);
    cudaGetSymbolAddress((void**)&p_bl2,g_bl2);
    cudaGetSymbolAddress((void**)&p_bhq,g_bhq);
    cudaGetSymbolAddress((void**)&p_blq,g_blq);
    cudaGetSymbolAddress((void**)&p_bhk,g_bhk);
    cudaGetSymbolAddress((void**)&p_blk,g_blk);
    cudaGetSymbolAddress((void**)&p_bhv,g_bhv);
    cudaGetSymbolAddress((void**)&p_blv,g_blv);

    cudaFuncSetAttribute(gemm_mma_kernel<false,false>,
                         cudaFuncAttributeMaxDynamicSharedMemorySize, SM_TOTAL);
    cudaFuncSetAttribute(gemm_mma_kernel<true,true>,
                         cudaFuncAttributeMaxDynamicSharedMemorySize, SM_TOTAL);
    cudaFuncSetAttribute(gemm_attn_kernel,
                         cudaFuncAttributeMaxDynamicSharedMemorySize, SM_TOTAL);

    // Launch order: slot #4 (ncu capture) = knn_kernel (verify its delta).
    bprep5_kernel<<<dim3(NC,5),NC>>>(g1w, g2w, wq, wk, wv);
    gemm_mma_kernel<false,false><<<dim3(NPTS/128,2),256,SM_TOTAL>>>(feat, p_bhq, p_blq, bq, nullptr, p_q,  nullptr, nullptr);
    gemm_mma_kernel<false,false><<<dim3(NPTS/128,2),256,SM_TOTAL>>>(feat, p_bhk, p_blk, bk, nullptr, p_kf, nullptr, nullptr);
    knn_kernel<<<dim3(NP/8, NB), 256>>>(xyz);
    gemm_mma_kernel<false,false><<<dim3(NPTS/128,2),256,SM_TOTAL>>>(feat, p_bhv, p_blv, bv, nullptr, p_vf, nullptr, nullptr);
    dstat_kernel<<<512,256>>>(xyz, d1w, d1b);
    dfin_kernel<<<1,32>>>(bndg, bndb);
    hprod_kernel<<<512,256>>>(xyz, d1w, d1b, d2w, d2b);
    bnfin_kernel<<<1,256>>>(p_ps1, p_pq1, 512, g1g, g1bt, p_bn1);
    gemm_mma_kernel<true,true><<<dim3(NROWS/128,2),256,SM_TOTAL>>>(p_h, p_bh1, p_bl1, g1b, p_bn1, p_h2, p_ps2, p_pq2);
    bnfin_kernel<<<1,256>>>(p_ps2, p_pq2, 2048, g2g, g2bt, p_bn2);
    gemm_attn_kernel<<<dim3(NROWS/128,2),256,SM_TOTAL>>>(
        p_h2, p_bh2, p_bl2, g2b, p_bn2, d2w, d2b, out);
}

// round 16
// speedup vs baseline: 1.9921x; 1.2109x over previous
#include <cuda_runtime.h>
#include <cuda_bf16.h>
#include <math.h>
#include <float.h>

#define NB 4
#define NP 4096
#define NC 256
#define NK 16
#define NPTS (NB*NP)      /* 16384 */
#define NROWS (NPTS*NK)   /* 262144 */

// ---------------- scratch (device globals; no allocation) ----------------
__device__ float g_q [NPTS*NC];
__device__ float g_kf[NPTS*NC];
__device__ float g_vf[NPTS*NC];
__device__ int   g_idx[NROWS];
__device__ float g_u [NROWS*3];
__device__ float g_h [NROWS*NC];
__device__ float g_h2[NROWS*NC];
__device__ float g_bnd[6];
__device__ float g_partd[512*6];
__device__ float g_ps1[512*NC];
__device__ float g_pq1[512*NC];
__device__ float g_ps2[2048*NC];
__device__ float g_pq2[2048*NC];
__device__ float g_bn1[2*NC];
__device__ float g_bn2[2*NC];
__device__ __nv_bfloat16 g_bh1[NC*NC], g_bl1[NC*NC];
__device__ __nv_bfloat16 g_bh2[NC*NC], g_bl2[NC*NC];
__device__ __nv_bfloat16 g_bhq[NC*NC], g_blq[NC*NC];
__device__ __nv_bfloat16 g_bhk[NC*NC], g_blk[NC*NC];
__device__ __nv_bfloat16 g_bhv[NC*NC], g_blv[NC*NC];

// ---------------- exact-rounding helpers for KNN ----------------
__device__ __forceinline__ float sq3_exact(float x, float y, float z){
    return __fadd_rn(__fadd_rn(__fmul_rn(x,x), __fmul_rn(y,y)), __fmul_rn(z,z));
}
__device__ __forceinline__ float dist_exact(float qx,float qy,float qz,float qw,
                                            float px,float py,float pz,float pw){
    float dot = __fmaf_rn(qz, pz, __fmaf_rn(qy, py, __fmul_rn(qx, px)));
    return __fsub_rn(__fadd_rn(qw, pw), __fmul_rn(2.0f, dot));
}
__device__ __forceinline__ bool lex_less(float d0,int i0,float d1,int i1){
    return d0 < d1 || (d0 == d1 && i0 < i1);
}

// ---------------- KNN: warp-cooperative distributed sorted top-16 ----------------
// Lane j<16 holds global list entry j (lex (d,idx) ascending). Threshold = entry 15.
// Candidates that beat the threshold are ballot-serialized into the list.
__global__ __launch_bounds__(256, 4) void knn_kernel(const float* __restrict__ xyz)
{
    constexpr int CH = 2048;
    __shared__ float4 pts[CH];
    int b = blockIdx.y;
    const float* xb = xyz + b*NP*3;
    int warp = threadIdx.x >> 5, lane = threadIdx.x & 31;
    int n = blockIdx.x*8 + warp;
    float qx = xb[n*3+0], qy = xb[n*3+1], qz = xb[n*3+2];
    float qw = sq3_exact(qx, qy, qz);

    float ld = FLT_MAX; int li = 0x7fffffff;   // list entry (lanes 0..15 meaningful)
    float td = FLT_MAX; int ti = 0x7fffffff;   // threshold = entry 15

    for (int c0=0;c0<NP;c0+=CH){
        __syncthreads();
        for (int i=threadIdx.x;i<CH;i+=256){
            int m=c0+i;
            float x=xb[m*3],y=xb[m*3+1],z=xb[m*3+2];
            pts[i]=make_float4(x,y,z, sq3_exact(x,y,z));
        }
        __syncthreads();
        for (int i=lane;i<CH;i+=32){
            float4 p=pts[i];
            int m=c0+i;
            float d = dist_exact(qx,qy,qz,qw, p.x,p.y,p.z,p.w);
            unsigned cand = __ballot_sync(0xffffffffu, lex_less(d,m, td,ti));
            while (cand){
                int src = __ffs(cand)-1;
                float dw = __shfl_sync(0xffffffffu, d, src);
                int   iw = __shfl_sync(0xffffffffu, m, src);
                // sorted shift-insert into distributed list
                float pd = __shfl_up_sync(0xffffffffu, ld, 1);
                int   pi = __shfl_up_sync(0xffffffffu, li, 1);
                if (lane==0){ pd = -FLT_MAX; pi = -1; }
                bool wl_cur  = lex_less(dw,iw, ld,li);
                bool wl_prev = lex_less(dw,iw, pd,pi);
                if (wl_cur){
                    if (wl_prev){ ld = pd; li = pi; }
                    else        { ld = dw; li = iw; }
                }
                td = __shfl_sync(0xffffffffu, ld, 15);
                ti = __shfl_sync(0xffffffffu, li, 15);
                cand &= ~(1u << src);
                bool still = ((cand >> lane) & 1u) && lex_less(d,m, td,ti);
                cand = __ballot_sync(0xffffffffu, still);
            }
        }
    }
    if (lane < NK) g_idx[(b*NP+n)*NK + lane] = li;
}

// ---------------- d-path BN stats ----------------
__global__ __launch_bounds__(256) void dstat_kernel(const float* __restrict__ xyz,
                                                    const float* __restrict__ d1w,
                                                    const float* __restrict__ d1b)
{
    float s[3]={0.f,0.f,0.f}, sq[3]={0.f,0.f,0.f};
    int stride = gridDim.x*blockDim.x;
    for (int it = blockIdx.x*blockDim.x+threadIdx.x; it < NROWS; it += stride){
        int pt = it >> 4;
        int b  = pt >> 12;
        int j  = g_idx[it];
        float r0 = xyz[pt*3+0] - xyz[(b*NP+j)*3+0];
        float r1 = xyz[pt*3+1] - xyz[(b*NP+j)*3+1];
        float r2 = xyz[pt*3+2] - xyz[(b*NP+j)*3+2];
#pragma unroll
        for (int d=0;d<3;d++){
            float t = r0*d1w[d] + r1*d1w[3+d] + r2*d1w[6+d] + d1b[d];
            s[d]+=t; sq[d]+=t*t;
        }
    }
    __shared__ float red[256];
    for (int q=0;q<6;q++){
        red[threadIdx.x] = (q<3)? s[q] : sq[q-3];
        __syncthreads();
        for (int st=128; st; st>>=1){
            if (threadIdx.x<st) red[threadIdx.x]+=red[threadIdx.x+st];
            __syncthreads();
        }
        if (threadIdx.x==0) g_partd[blockIdx.x*6+q]=red[0];
        __syncthreads();
    }
}

__global__ void dfin_kernel(const float* __restrict__ g, const float* __restrict__ beta)
{
    int d = threadIdx.x;
    if (d>=3) return;
    double s=0.0,q=0.0;
    for (int i=0;i<512;i++){ s+=g_partd[i*6+d]; q+=g_partd[i*6+3+d]; }
    double m = s/(double)NROWS;
    double v = q/(double)NROWS - m*m;
    double sc = (double)g[d] / sqrt(v+1e-5);
    g_bnd[d]   = (float)sc;
    g_bnd[3+d] = (float)((double)beta[d] - m*sc);
}

// ---------------- weight prep (all 5 matrices, one launch) ----------------
__global__ void bprep5_kernel(const float* __restrict__ g1w, const float* __restrict__ g2w,
                              const float* __restrict__ wq,  const float* __restrict__ wk,
                              const float* __restrict__ wv)
{
    int k = blockIdx.x, n = threadIdx.x;
    const float* W; __nv_bfloat16 *H, *L;
    switch (blockIdx.y){
        case 0: W=g1w; H=g_bh1; L=g_bl1; break;
        case 1: W=g2w; H=g_bh2; L=g_bl2; break;
        case 2: W=wq;  H=g_bhq; L=g_blq; break;
        case 3: W=wk;  H=g_bhk; L=g_blk; break;
        default:W=wv;  H=g_bhv; L=g_blv; break;
    }
    float w = W[k*NC+n];
    __nv_bfloat16 h = __float2bfloat16_rn(w);
    H[n*NC+k] = h;
    L[n*NC+k] = __float2bfloat16_rn(w - __bfloat162float(h));
}

// ---------------- HMMA helpers ----------------
__device__ __forceinline__ void mma_bf16(float* c, const unsigned* a, const unsigned* b){
    asm volatile(
      "mma.sync.aligned.m16n8k16.row.col.f32.bf16.bf16.f32 "
      "{%0,%1,%2,%3}, {%4,%5,%6,%7}, {%8,%9}, {%0,%1,%2,%3};"
      : "+f"(c[0]),"+f"(c[1]),"+f"(c[2]),"+f"(c[3])
      : "r"(a[0]),"r"(a[1]),"r"(a[2]),"r"(a[3]), "r"(b[0]),"r"(b[1]));
}
__device__ __forceinline__ void ldmx4(unsigned* r, unsigned addr){
    asm volatile("ldmatrix.sync.aligned.m8n8.x4.shared.b16 {%0,%1,%2,%3}, [%4];"
                 : "=r"(r[0]),"=r"(r[1]),"=r"(r[2]),"=r"(r[3]) : "r"(addr));
}
__device__ __forceinline__ void cpa16(unsigned dst, const void* src){
    asm volatile("cp.async.cg.shared.global [%0], [%1], 16;" :: "r"(dst), "l"(src));
}
#define CPA_COMMIT asm volatile("cp.async.commit_group;" ::: "memory")
#define CPA_WAIT0  asm volatile("cp.async.wait_group 0;" ::: "memory")

#define KC 32           /* K-chunk */
#define RSTRIDE 40      /* bf16 tile row stride in halves: 80B, ldmatrix conflict-free */
#define ATILE 10240     /* bytes per 128xKC bf16 tile */
#define AFSTRIDE 36     /* fp32 A staging row stride in words */
// dynamic smem layout
#define SM_ASH 0
#define SM_ASL ATILE
#define SM_BH(buf) (2*ATILE + (buf)*2*ATILE)
#define SM_BL(buf) (3*ATILE + (buf)*2*ATILE)
#define SM_AF(buf) (6*ATILE + (buf)*(128*AFSTRIDE*4))
#define SM_TOTAL (6*ATILE + 2*(128*AFSTRIDE*4))   /* 98304 */

// Shared mainloop: cp.async double-buffered pipeline, 3 sequential HMMA passes.
template<bool BNRELU>
__device__ __forceinline__ void gemm_mainloop(
    const float* __restrict__ A, const __nv_bfloat16* __restrict__ Bh,
    const __nv_bfloat16* __restrict__ Bl, const float* __restrict__ bnp,
    char* dsm, size_t rowbase, int ncb, int tid, int wm, int wn,
    float acc[2][8][4])
{
    int lane = tid & 31;
    int lr = tid >> 1;
    int cg = (tid & 1) * 16;
    int q3 = lane >> 3, rl = lane & 7;
    unsigned sb = (unsigned)__cvta_generic_to_shared(dsm);
    unsigned aoffA = (unsigned)(((wm*32 + (q3&1)*8 + rl) * RSTRIDE + (q3>>1)*8) * 2);
    unsigned aoffB = (unsigned)(((wn*64 + (q3>>1)*8 + rl) * RSTRIDE + (q3&1)*8) * 2);

    const float*         asrc0 = A  + (rowbase + lr)*256 + cg;
    const __nv_bfloat16* bhs0  = Bh + (size_t)(ncb + lr)*256 + cg;
    const __nv_bfloat16* bls0  = Bl + (size_t)(ncb + lr)*256 + cg;
    unsigned adst_r = (unsigned)((lr*AFSTRIDE + cg)*4);
    unsigned bdst_r = (unsigned)((lr*RSTRIDE  + cg)*2);

    // prologue: chunk 0 -> buffers 0
    {
        unsigned ad = sb + SM_AF(0) + adst_r;
        cpa16(ad,    asrc0);     cpa16(ad+16, asrc0+4);
        cpa16(ad+32, asrc0+8);   cpa16(ad+48, asrc0+12);
        unsigned bh = sb + SM_BH(0) + bdst_r;
        unsigned bl = sb + SM_BL(0) + bdst_r;
        cpa16(bh, bhs0); cpa16(bh+16, bhs0+8);
        cpa16(bl, bls0); cpa16(bl+16, bls0+8);
        CPA_COMMIT;
    }

    for (int ic = 0; ic < 8; ic++){
        int buf = ic & 1;
        CPA_WAIT0;
        __syncthreads();

        if (ic < 7){
            int kc1 = (ic+1)*KC;
            unsigned ad = sb + SM_AF(buf^1) + adst_r;
            const float* as = asrc0 + kc1;
            cpa16(ad,    as);    cpa16(ad+16, as+4);
            cpa16(ad+32, as+8);  cpa16(ad+48, as+12);
            unsigned bh = sb + SM_BH(buf^1) + bdst_r;
            unsigned bl = sb + SM_BL(buf^1) + bdst_r;
            cpa16(bh, bhs0 + kc1); cpa16(bh+16, bhs0 + kc1 + 8);
            cpa16(bl, bls0 + kc1); cpa16(bl+16, bls0 + kc1 + 8);
            CPA_COMMIT;
        }

        // convert A chunk ic: smem fp32 -> bnrelu -> bf16 hi/lo tiles
        {
            int kc0 = ic*KC;
            const float* af = (const float*)(dsm + SM_AF(buf)) + lr*AFSTRIDE + cg;
            float v[16];
            *(float4*)(v)    = *(const float4*)(af);
            *(float4*)(v+4)  = *(const float4*)(af+4);
            *(float4*)(v+8)  = *(const float4*)(af+8);
            *(float4*)(v+12) = *(const float4*)(af+12);
            unsigned hh[8], ll[8];
#pragma unroll
            for (int p=0;p<8;p++){
                float a0 = v[p*2], a1 = v[p*2+1];
                if (BNRELU){
                    int c = kc0 + cg + p*2;
                    a0 = fmaxf(0.f, fmaf(a0, bnp[c],   bnp[256+c]));
                    a1 = fmaxf(0.f, fmaf(a1, bnp[c+1], bnp[257+c]));
                }
                __nv_bfloat16 h0 = __float2bfloat16_rn(a0);
                __nv_bfloat16 h1 = __float2bfloat16_rn(a1);
                __nv_bfloat16 l0 = __float2bfloat16_rn(a0 - __bfloat162float(h0));
                __nv_bfloat16 l1 = __float2bfloat16_rn(a1 - __bfloat162float(h1));
                hh[p] = (unsigned)__bfloat16_as_ushort(h0) | ((unsigned)__bfloat16_as_ushort(h1)<<16);
                ll[p] = (unsigned)__bfloat16_as_ushort(l0) | ((unsigned)__bfloat16_as_ushort(l1)<<16);
            }
            unsigned short (*AsH)[RSTRIDE] = (unsigned short(*)[RSTRIDE])(dsm + SM_ASH);
            unsigned short (*AsL)[RSTRIDE] = (unsigned short(*)[RSTRIDE])(dsm + SM_ASL);
            *(uint4*)&AsH[lr][cg]   = make_uint4(hh[0],hh[1],hh[2],hh[3]);
            *(uint4*)&AsH[lr][cg+8] = make_uint4(hh[4],hh[5],hh[6],hh[7]);
            *(uint4*)&AsL[lr][cg]   = make_uint4(ll[0],ll[1],ll[2],ll[3]);
            *(uint4*)&AsL[lr][cg+8] = make_uint4(ll[4],ll[5],ll[6],ll[7]);
        }
        __syncthreads();

        unsigned aASH = sb + SM_ASH, aASL = sb + SM_ASL;
        unsigned aBH  = sb + SM_BH(buf), aBL = sb + SM_BL(buf);
#pragma unroll
        for (int p=0;p<3;p++){
            unsigned Abase = (p==2)? aASL : aASH;
            unsigned Bbase = (p==1)? aBL  : aBH;
#pragma unroll
            for (int ks=0; ks<KC; ks+=16){
                unsigned af[2][4];
#pragma unroll
                for (int mt=0;mt<2;mt++)
                    ldmx4(af[mt], Abase + aoffA + (unsigned)((mt*16*RSTRIDE + ks)*2));
#pragma unroll
                for (int ntp=0;ntp<4;ntp++){
                    unsigned bb[4];
                    ldmx4(bb, Bbase + aoffB + (unsigned)((ntp*16*RSTRIDE + ks)*2));
                    mma_bf16(acc[0][2*ntp],   af[0], bb);
                    mma_bf16(acc[1][2*ntp],   af[1], bb);
                    mma_bf16(acc[0][2*ntp+1], af[0], bb+2);
                    mma_bf16(acc[1][2*ntp+1], af[1], bb+2);
                }
            }
        }
    }
}

// ---------------- GEMM (qkv / gamma1): store C, optional BN+fused stats ----------------
template<bool BNRELU, bool STATS>
__global__ __launch_bounds__(256, 2) void gemm_mma_kernel(
    const float* __restrict__ A,
    const __nv_bfloat16* __restrict__ Bh, const __nv_bfloat16* __restrict__ Bl,
    const float* __restrict__ bias, const float* __restrict__ bnp,
    float* __restrict__ C, float* __restrict__ psum, float* __restrict__ psq)
{
    extern __shared__ __align__(128) char dsm[];

    int tid = threadIdx.x, wid = tid >> 5, lane = tid & 31;
    int g = lane >> 2, t = lane & 3;
    int wm = wid & 3, wn = wid >> 2;
    const size_t rowbase = (size_t)blockIdx.x * 128;
    const int ncb = blockIdx.y * 128;

    float acc[2][8][4];
#pragma unroll
    for (int mt=0;mt<2;mt++)
#pragma unroll
        for (int nt=0;nt<8;nt++)
#pragma unroll
            for (int i=0;i<4;i++) acc[mt][nt][i]=0.f;

    gemm_mainloop<BNRELU>(A, Bh, Bl, bnp, dsm, rowbase, ncb, tid, wm, wn, acc);

#pragma unroll
    for (int nt=0;nt<8;nt++){
        int col = ncb + wn*64 + nt*8 + 2*t;
        float b0 = bias[col], b1 = bias[col+1];
#pragma unroll
        for (int mt=0;mt<2;mt++){
            acc[mt][nt][0]+=b0; acc[mt][nt][1]+=b1;
            acc[mt][nt][2]+=b0; acc[mt][nt][3]+=b1;
        }
    }
#pragma unroll
    for (int nt=0;nt<8;nt++){
        int col = ncb + wn*64 + nt*8 + 2*t;
#pragma unroll
        for (int mt=0;mt<2;mt++){
            size_t row = rowbase + wm*32 + mt*16 + g;
            *(float2*)&C[row*256 + col]     = make_float2(acc[mt][nt][0], acc[mt][nt][1]);
            *(float2*)&C[(row+8)*256 + col] = make_float2(acc[mt][nt][2], acc[mt][nt][3]);
        }
    }

    if (STATS){
        __syncthreads();
        float* sS = (float*)dsm;              // [4][128]
        float* sQ = sS + 512;
#pragma unroll
        for (int nt=0;nt<8;nt++){
            float s0=0.f,q0=0.f,s1=0.f,q1=0.f;
#pragma unroll
            for (int mt=0;mt<2;mt++){
                float v0=acc[mt][nt][0], v2=acc[mt][nt][2];
                float v1=acc[mt][nt][1], v3=acc[mt][nt][3];
                s0 += v0+v2;  q0 += v0*v0+v2*v2;
                s1 += v1+v3;  q1 += v1*v1+v3*v3;
            }
#pragma unroll
            for (int off=16; off>=4; off>>=1){
                s0 += __shfl_down_sync(0xffffffffu, s0, off);
                q0 += __shfl_down_sync(0xffffffffu, q0, off);
                s1 += __shfl_down_sync(0xffffffffu, s1, off);
                q1 += __shfl_down_sync(0xffffffffu, q1, off);
            }
            if (lane < 4){
                int c = wn*64 + nt*8 + 2*lane;
                sS[wm*128 + c]     = s0;  sS[wm*128 + c + 1] = s1;
                sQ[wm*128 + c]     = q0;  sQ[wm*128 + c + 1] = q1;
            }
        }
        __syncthreads();
        if (tid < 128){
            float s = sS[tid] + sS[128+tid] + sS[256+tid] + sS[384+tid];
            float q = sQ[tid] + sQ[128+tid] + sQ[256+tid] + sQ[384+tid];
            psum[blockIdx.x*256 + ncb + tid] = s;
            psq [blockIdx.x*256 + ncb + tid] = q;
        }
    }
}

// ---------------- fused gamma2 + softmax(K) + weighted output ----------------
#define VSTRIDE 132
__global__ __launch_bounds__(256, 2) void gemm_attn_kernel(
    const float* __restrict__ A,
    const __nv_bfloat16* __restrict__ Bh, const __nv_bfloat16* __restrict__ Bl,
    const float* __restrict__ bias, const float* __restrict__ bnp,
    const float* __restrict__ d2w, const float* __restrict__ d2b,
    float* __restrict__ out)
{
    extern __shared__ __align__(128) char dsm[];
    float* Vs = (float*)dsm;                     // reused after mainloop: 128 x VSTRIDE

    int tid = threadIdx.x, wid = tid >> 5, lane = tid & 31;
    int g = lane >> 2, t = lane & 3;
    int wm = wid & 3, wn = wid >> 2;
    const size_t rowbase = (size_t)blockIdx.x * 128;
    const int ncb = blockIdx.y * 128;

    float acc[2][8][4];
#pragma unroll
    for (int mt=0;mt<2;mt++)
#pragma unroll
        for (int nt=0;nt<8;nt++)
#pragma unroll
            for (int i=0;i<4;i++) acc[mt][nt][i]=0.f;

    gemm_mainloop<true>(A, Bh, Bl, bnp, dsm, rowbase, ncb, tid, wm, wn, acc);

    // bias -> logits
#pragma unroll
    for (int nt=0;nt<8;nt++){
        int col = ncb + wn*64 + nt*8 + 2*t;
        float b0 = bias[col], b1 = bias[col+1];
#pragma unroll
        for (int mt=0;mt<2;mt++){
            acc[mt][nt][0]+=b0; acc[mt][nt][1]+=b1;
            acc[mt][nt][2]+=b0; acc[mt][nt][3]+=b1;
        }
    }

    __syncthreads();   // tiles no longer needed; reuse as Vs

    // stage gathered v rows
    {
        int r = tid >> 1;
        int half = (tid & 1) * 64;
        size_t grow = rowbase + r;
        int gpt = (int)(grow >> 4);
        int b = gpt >> 12;
        int j = g_idx[grow];
        const float* vp = g_vf + ((size_t)(b*NP + j))*256 + ncb + half;
        float* dst = Vs + r*VSTRIDE + half;
#pragma unroll
        for (int i=0;i<16;i++)
            *(float4*)(dst + i*4) = *(const float4*)(vp + i*4);
    }

    // softmax over K — register + shfl only
#pragma unroll
    for (int mt=0;mt<2;mt++)
#pragma unroll
    for (int nt=0;nt<8;nt++){
        float a0=acc[mt][nt][0], a1=acc[mt][nt][1], a2=acc[mt][nt][2], a3=acc[mt][nt][3];
        float m0 = fmaxf(a0,a2), m1 = fmaxf(a1,a3);
#pragma unroll
        for (int mk=4; mk<=16; mk<<=1){
            m0 = fmaxf(m0, __shfl_xor_sync(0xffffffffu, m0, mk));
            m1 = fmaxf(m1, __shfl_xor_sync(0xffffffffu, m1, mk));
        }
        float e0=expf(a0-m0), e2=expf(a2-m0), e1=expf(a1-m1), e3=expf(a3-m1);
        float s0=e0+e2, s1=e1+e3;
#pragma unroll
        for (int mk=4; mk<=16; mk<<=1){
            s0 += __shfl_xor_sync(0xffffffffu, s0, mk);
            s1 += __shfl_xor_sync(0xffffffffu, s1, mk);
        }
        float i0=1.f/s0, i1=1.f/s1;
        acc[mt][nt][0]=e0*i0; acc[mt][nt][1]=e1*i1;
        acc[mt][nt][2]=e2*i0; acc[mt][nt][3]=e3*i1;
    }

    // u vectors for this thread's 2x2 k-rows
    float3 uv[2][2];
#pragma unroll
    for (int mt=0;mt<2;mt++)
#pragma unroll
    for (int kk=0;kk<2;kk++){
        size_t r = rowbase + wm*32 + mt*16 + g + kk*8;
        uv[mt][kk] = make_float3(g_u[r*3], g_u[r*3+1], g_u[r*3+2]);
    }

    __syncthreads();   // Vs ready

    // weighted output
#pragma unroll
    for (int nt=0;nt<8;nt++){
        int c0 = wn*64 + nt*8 + 2*t;
        int gc = ncb + c0;
        float w0a=d2w[gc],   w1a=d2w[256+gc],   w2a=d2w[512+gc],   ba=d2b[gc];
        float w0b=d2w[gc+1], w1b=d2w[257+gc],   w2b=d2w[513+gc],   bb=d2b[gc+1];
#pragma unroll
        for (int mt=0;mt<2;mt++){
            float o0=0.f, o1=0.f;
#pragma unroll
            for (int kk=0;kk<2;kk++){
                int r = wm*32 + mt*16 + g + kk*8;
                float2 v = *(const float2*)&Vs[r*VSTRIDE + c0];
                float3 u = uv[mt][kk];
                float pea = u.x*w0a + u.y*w1a + u.z*w2a + ba;
                float peb = u.x*w0b + u.y*w1b + u.z*w2b + bb;
                o0 += acc[mt][nt][kk*2+0] * (v.x + pea);
                o1 += acc[mt][nt][kk*2+1] * (v.y + peb);
            }
#pragma unroll
            for (int mk=4; mk<=16; mk<<=1){
                o0 += __shfl_xor_sync(0xffffffffu, o0, mk);
                o1 += __shfl_xor_sync(0xffffffffu, o1, mk);
            }
            if (g == 0){
                size_t pt = (rowbase >> 4) + 2*wm + mt;
                *(float2*)&out[pt*256 + gc] = make_float2(o0, o1);
            }
        }
    }
}

// ---------------- finalize per-channel BN over 256 channels ----------------
__global__ __launch_bounds__(256) void bnfin_kernel(const float* __restrict__ psum,
                                                    const float* __restrict__ psq, int P,
                                                    const float* __restrict__ g,
                                                    const float* __restrict__ beta,
                                                    float* __restrict__ outp)
{
    int c = threadIdx.x;
    double s=0.0,q=0.0;
    for (int i=0;i<P;i++){ s+=psum[i*NC+c]; q+=psq[i*NC+c]; }
    double m = s/(double)NROWS;
    double v = q/(double)NROWS - m*m;
    double sc = (double)g[c] / sqrt(v+1e-5);
    outp[c]    = (float)sc;
    outp[NC+c] = (float)((double)beta[c] - m*sc);
}

// ---------------- h producer ----------------
__global__ __launch_bounds__(256) void hprod_kernel(
    const float* __restrict__ xyz, const float* __restrict__ d1w, const float* __restrict__ d1b,
    const float* __restrict__ d2w, const float* __restrict__ d2b)
{
    __shared__ float su[NK*3];
    __shared__ int   sj[NK];
    int c = threadIdx.x;
    float d2c0 = d2w[c], d2c1 = d2w[256+c], d2c2 = d2w[512+c], d2bc = d2b[c];
    float s=0.f, q=0.f;
    for (int pp=0; pp<32; pp++){
        int pt = blockIdx.x*32 + pp;
        int b  = pt >> 12;
        if (c < NK){
            int k = c;
            int j = g_idx[pt*NK+k];
            sj[k]=j;
            float r0 = xyz[pt*3+0]-xyz[(b*NP+j)*3+0];
            float r1 = xyz[pt*3+1]-xyz[(b*NP+j)*3+1];
            float r2 = xyz[pt*3+2]-xyz[(b*NP+j)*3+2];
#pragma unroll
            for (int d=0;d<3;d++){
                float t  = r0*d1w[d] + r1*d1w[3+d] + r2*d1w[6+d] + d1b[d];
                float uu = fmaxf(0.f, fmaf(t, g_bnd[d], g_bnd[3+d]));
                su[k*3+d]=uu;
                g_u[(pt*NK+k)*3+d]=uu;
            }
        }
        __syncthreads();
        float qv = g_q[pt*NC + c];
#pragma unroll
        for (int k=0;k<NK;k++){
            int j = sj[k];
            float kv = g_kf[(b*NP+j)*NC + c];
            float pe = su[k*3]*d2c0 + su[k*3+1]*d2c1 + su[k*3+2]*d2c2 + d2bc;
            float h = qv - kv + pe;
            g_h[(size_t)(pt*NK+k)*NC + c] = h;
            s += h; q += h*h;
        }
        __syncthreads();
    }
    g_ps1[blockIdx.x*NC+c]=s;
    g_pq1[blockIdx.x*NC+c]=q;
}

// ---------------- host launcher ----------------
extern "C" void kernel_launch(void* const* d_in, const int* in_sizes, int n_in,
                              void* d_out, int out_size)
{
    const float* xyz  = (const float*)d_in[0];
    const float* feat = (const float*)d_in[1];
    const float* wq   = (const float*)d_in[2];  const float* bq  = (const float*)d_in[3];
    const float* wk   = (const float*)d_in[4];  const float* bk  = (const float*)d_in[5];
    const float* wv   = (const float*)d_in[6];  const float* bv  = (const float*)d_in[7];
    const float* d1w  = (const float*)d_in[8];  const float* d1b = (const float*)d_in[9];
    const float* bndg = (const float*)d_in[10]; const float* bndb= (const float*)d_in[11];
    const float* d2w  = (const float*)d_in[12]; const float* d2b = (const float*)d_in[13];
    const float* g1g  = (const float*)d_in[14]; const float* g1bt= (const float*)d_in[15];
    const float* g1w  = (const float*)d_in[16]; const float* g1b = (const float*)d_in[17];
    const float* g2g  = (const float*)d_in[18]; const float* g2bt= (const float*)d_in[19];
    const float* g2w  = (const float*)d_in[20]; const float* g2b = (const float*)d_in[21];
    float* out = (float*)d_out;

    float *p_q,*p_kf,*p_vf,*p_h,*p_h2,*p_bn1,*p_bn2,*p_ps1,*p_pq1,*p_ps2,*p_pq2;
    __nv_bfloat16 *p_bh1,*p_bl1,*p_bh2,*p_bl2,*p_bhq,*p_blq,*p_bhk,*p_blk,*p_bhv,*p_blv;
    cudaGetSymbolAddress((void**)&p_q,  g_q);
    cudaGetSymbolAddress((void**)&p_kf, g_kf);
    cudaGetSymbolAddress((void**)&p_vf, g_vf);
    cudaGetSymbolAddress((void**)&p_h,  g_h);
    cudaGetSymbolAddress((void**)&p_h2, g_h2);
    cudaGetSymbolAddress((void**)&p_bn1,g_bn1);
    cudaGetSymbolAddress((void**)&p_bn2,g_bn2);
    cudaGetSymbolAddress((void**)&p_ps1,g_ps1);
    cudaGetSymbolAddress((void**)&p_pq1,g_pq1);
    cudaGetSymbolAddress((void**)&p_ps2,g_ps2);
    cudaGetSymbolAddress((void**)&p_pq2,g_pq2);
    cudaGetSymbolAddress((void**)&p_bh1,g_bh1);
    cudaGetSymbolAddress((void**)&p_bl1,g_bl1);
    cudaGetSymbolAddress((void**)&p_bh2,g_bh2);
    cudaGetSymbolAddress((void**)&p_bl2,g_bl2);
    cudaGetSymbolAddress((void**)&p_bhq,g_bhq);
    cudaGetSymbolAddress((void**)&p_blq,g_blq);
    cudaGetSymbolAddress((void**)&p_bhk,g_bhk);
    cudaGetSymbolAddress((void**)&p_blk,g_blk);
    cudaGetSymbolAddress((void**)&p_bhv,g_bhv);
    cudaGetSymbolAddress((void**)&p_blv,g_blv);

    cudaFuncSetAttribute(gemm_mma_kernel<false,false>,
                         cudaFuncAttributeMaxDynamicSharedMemorySize, SM_TOTAL);
    cudaFuncSetAttribute(gemm_mma_kernel<true,true>,
                         cudaFuncAttributeMaxDynamicSharedMemorySize, SM_TOTAL);
    cudaFuncSetAttribute(gemm_attn_kernel,
                         cudaFuncAttributeMaxDynamicSharedMemorySize, SM_TOTAL);

    // Launch order: slot #4 (ncu capture) = knn_kernel (verify its delta).
    bprep5_kernel<<<dim3(NC,5),NC>>>(g1w, g2w, wq, wk, wv);
    gemm_mma_kernel<false,false><<<dim3(NPTS/128,2),256,SM_TOTAL>>>(feat, p_bhq, p_blq, bq, nullptr, p_q,  nullptr, nullptr);
    gemm_mma_kernel<false,false><<<dim3(NPTS/128,2),256,SM_TOTAL>>>(feat, p_bhk, p_blk, bk, nullptr, p_kf, nullptr, nullptr);
    knn_kernel<<<dim3(NP/8, NB), 256>>>(xyz);
    gemm_mma_kernel<false,false><<<dim3(NPTS/128,2),256,SM_TOTAL>>>(feat, p_bhv, p_blv, bv, nullptr, p_vf, nullptr, nullptr);
    dstat_kernel<<<512,256>>>(xyz, d1w, d1b);
    dfin_kernel<<<1,32>>>(bndg, bndb);
    hprod_kernel<<<512,256>>>(xyz, d1w, d1b, d2w, d2b);
    bnfin_kernel<<<1,256>>>(p_ps1, p_pq1, 512, g1g, g1bt, p_bn1);
    gemm_mma_kernel<true,true><<<dim3(NROWS/128,2),256,SM_TOTAL>>>(p_h, p_bh1, p_bl1, g1b, p_bn1, p_h2, p_ps2, p_pq2);
    bnfin_kernel<<<1,256>>>(p_ps2, p_pq2, 2048, g2g, g2bt, p_bn2);
    gemm_attn_kernel<<<dim3(NROWS/128,2),256,SM_TOTAL>>>(
        p_h2, p_bh2, p_bl2, g2b, p_bn2, d2w, d2b, out);
}

// round 17
// speedup vs baseline: 2.0136x; 1.0108x over previous
#include <cuda_runtime.h>
#include <cuda_bf16.h>
#include <math.h>
#include <float.h>

#define NB 4
#define NP 4096
#define NC 256
#define NK 16
#define NPTS (NB*NP)      /* 16384 */
#define NROWS (NPTS*NK)   /* 262144 */

// ---------------- scratch (device globals; no allocation) ----------------
__device__ float g_q [NPTS*NC];
__device__ float g_kf[NPTS*NC];
__device__ float g_vf[NPTS*NC];
__device__ int   g_idx[NROWS];
__device__ float g_u [NROWS*3];
__device__ float g_h [NROWS*NC];
__device__ float g_h2[NROWS*NC];
__device__ float g_bnd[6];
__device__ float g_partd[512*6];
__device__ float g_ps1[512*NC];
__device__ float g_pq1[512*NC];
__device__ float g_ps2[2048*NC];
__device__ float g_pq2[2048*NC];
__device__ float g_bn1[2*NC];
__device__ float g_bn2[2*NC];
__device__ __nv_bfloat16 g_bh1[NC*NC], g_bl1[NC*NC];
__device__ __nv_bfloat16 g_bh2[NC*NC], g_bl2[NC*NC];
__device__ __nv_bfloat16 g_bhq[NC*NC], g_blq[NC*NC];
__device__ __nv_bfloat16 g_bhk[NC*NC], g_blk[NC*NC];
__device__ __nv_bfloat16 g_bhv[NC*NC], g_blv[NC*NC];

// ---------------- exact-rounding helpers for KNN ----------------
__device__ __forceinline__ float sq3_exact(float x, float y, float z){
    return __fadd_rn(__fadd_rn(__fmul_rn(x,x), __fmul_rn(y,y)), __fmul_rn(z,z));
}
__device__ __forceinline__ float dist_exact(float qx,float qy,float qz,float qw,
                                            float px,float py,float pz,float pw){
    float dot = __fmaf_rn(qz, pz, __fmaf_rn(qy, py, __fmul_rn(qx, px)));
    return __fsub_rn(__fadd_rn(qw, pw), __fmul_rn(2.0f, dot));
}
__device__ __forceinline__ bool lex_less(float d0,int i0,float d1,int i1){
    return d0 < d1 || (d0 == d1 && i0 < i1);
}

// ---------------- KNN: warp-cooperative distributed sorted top-16 ----------------
__global__ __launch_bounds__(256, 4) void knn_kernel(const float* __restrict__ xyz)
{
    constexpr int CH = 2048;
    __shared__ float4 pts[CH];
    int b = blockIdx.y;
    const float* xb = xyz + b*NP*3;
    int warp = threadIdx.x >> 5, lane = threadIdx.x & 31;
    int n = blockIdx.x*8 + warp;
    float qx = xb[n*3+0], qy = xb[n*3+1], qz = xb[n*3+2];
    float qw = sq3_exact(qx, qy, qz);

    float ld = FLT_MAX; int li = 0x7fffffff;
    float td = FLT_MAX; int ti = 0x7fffffff;

    for (int c0=0;c0<NP;c0+=CH){
        __syncthreads();
        for (int i=threadIdx.x;i<CH;i+=256){
            int m=c0+i;
            float x=xb[m*3],y=xb[m*3+1],z=xb[m*3+2];
            pts[i]=make_float4(x,y,z, sq3_exact(x,y,z));
        }
        __syncthreads();
        for (int i=lane;i<CH;i+=32){
            float4 p=pts[i];
            int m=c0+i;
            float d = dist_exact(qx,qy,qz,qw, p.x,p.y,p.z,p.w);
            unsigned cand = __ballot_sync(0xffffffffu, lex_less(d,m, td,ti));
            while (cand){
                int src = __ffs(cand)-1;
                float dw = __shfl_sync(0xffffffffu, d, src);
                int   iw = __shfl_sync(0xffffffffu, m, src);
                float pd = __shfl_up_sync(0xffffffffu, ld, 1);
                int   pi = __shfl_up_sync(0xffffffffu, li, 1);
                if (lane==0){ pd = -FLT_MAX; pi = -1; }
                bool wl_cur  = lex_less(dw,iw, ld,li);
                bool wl_prev = lex_less(dw,iw, pd,pi);
                if (wl_cur){
                    if (wl_prev){ ld = pd; li = pi; }
                    else        { ld = dw; li = iw; }
                }
                td = __shfl_sync(0xffffffffu, ld, 15);
                ti = __shfl_sync(0xffffffffu, li, 15);
                cand &= ~(1u << src);
                bool still = ((cand >> lane) & 1u) && lex_less(d,m, td,ti);
                cand = __ballot_sync(0xffffffffu, still);
            }
        }
    }
    if (lane < NK) g_idx[(b*NP+n)*NK + lane] = li;
}

// ---------------- d-path BN stats ----------------
__global__ __launch_bounds__(256) void dstat_kernel(const float* __restrict__ xyz,
                                                    const float* __restrict__ d1w,
                                                    const float* __restrict__ d1b)
{
    float s[3]={0.f,0.f,0.f}, sq[3]={0.f,0.f,0.f};
    int stride = gridDim.x*blockDim.x;
    for (int it = blockIdx.x*blockDim.x+threadIdx.x; it < NROWS; it += stride){
        int pt = it >> 4;
        int b  = pt >> 12;
        int j  = g_idx[it];
        float r0 = xyz[pt*3+0] - xyz[(b*NP+j)*3+0];
        float r1 = xyz[pt*3+1] - xyz[(b*NP+j)*3+1];
        float r2 = xyz[pt*3+2] - xyz[(b*NP+j)*3+2];
#pragma unroll
        for (int d=0;d<3;d++){
            float t = r0*d1w[d] + r1*d1w[3+d] + r2*d1w[6+d] + d1b[d];
            s[d]+=t; sq[d]+=t*t;
        }
    }
    __shared__ float red[256];
    for (int q=0;q<6;q++){
        red[threadIdx.x] = (q<3)? s[q] : sq[q-3];
        __syncthreads();
        for (int st=128; st; st>>=1){
            if (threadIdx.x<st) red[threadIdx.x]+=red[threadIdx.x+st];
            __syncthreads();
        }
        if (threadIdx.x==0) g_partd[blockIdx.x*6+q]=red[0];
        __syncthreads();
    }
}

__global__ void dfin_kernel(const float* __restrict__ g, const float* __restrict__ beta)
{
    int d = threadIdx.x;
    if (d>=3) return;
    double s=0.0,q=0.0;
    for (int i=0;i<512;i++){ s+=g_partd[i*6+d]; q+=g_partd[i*6+3+d]; }
    double m = s/(double)NROWS;
    double v = q/(double)NROWS - m*m;
    double sc = (double)g[d] / sqrt(v+1e-5);
    g_bnd[d]   = (float)sc;
    g_bnd[3+d] = (float)((double)beta[d] - m*sc);
}

// ---------------- weight prep (all 5 matrices, one launch) ----------------
__global__ void bprep5_kernel(const float* __restrict__ g1w, const float* __restrict__ g2w,
                              const float* __restrict__ wq,  const float* __restrict__ wk,
                              const float* __restrict__ wv)
{
    int k = blockIdx.x, n = threadIdx.x;
    const float* W; __nv_bfloat16 *H, *L;
    switch (blockIdx.y){
        case 0: W=g1w; H=g_bh1; L=g_bl1; break;
        case 1: W=g2w; H=g_bh2; L=g_bl2; break;
        case 2: W=wq;  H=g_bhq; L=g_blq; break;
        case 3: W=wk;  H=g_bhk; L=g_blk; break;
        default:W=wv;  H=g_bhv; L=g_blv; break;
    }
    float w = W[k*NC+n];
    __nv_bfloat16 h = __float2bfloat16_rn(w);
    H[n*NC+k] = h;
    L[n*NC+k] = __float2bfloat16_rn(w - __bfloat162float(h));
}

// ---------------- HMMA helpers ----------------
__device__ __forceinline__ void mma_bf16(float* c, const unsigned* a, const unsigned* b){
    asm volatile(
      "mma.sync.aligned.m16n8k16.row.col.f32.bf16.bf16.f32 "
      "{%0,%1,%2,%3}, {%4,%5,%6,%7}, {%8,%9}, {%0,%1,%2,%3};"
      : "+f"(c[0]),"+f"(c[1]),"+f"(c[2]),"+f"(c[3])
      : "r"(a[0]),"r"(a[1]),"r"(a[2]),"r"(a[3]), "r"(b[0]),"r"(b[1]));
}
__device__ __forceinline__ void ldmx4(unsigned* r, unsigned addr){
    asm volatile("ldmatrix.sync.aligned.m8n8.x4.shared.b16 {%0,%1,%2,%3}, [%4];"
                 : "=r"(r[0]),"=r"(r[1]),"=r"(r[2]),"=r"(r[3]) : "r"(addr));
}
__device__ __forceinline__ void cpa16(unsigned dst, const void* src){
    asm volatile("cp.async.cg.shared.global [%0], [%1], 16;" :: "r"(dst), "l"(src));
}
#define CPA_COMMIT asm volatile("cp.async.commit_group;" ::: "memory")
#define CPA_WAIT0  asm volatile("cp.async.wait_group 0;" ::: "memory")

#define KC 32           /* K-chunk */
#define RSTRIDE 40      /* bf16 tile row stride in halves: 80B, ldmatrix conflict-free */
#define ATILE 10240     /* bytes per 128xKC bf16 tile */
#define AFSTRIDE 36     /* fp32 A staging row stride in words */
// dynamic smem layout
#define SM_ASH 0
#define SM_ASL ATILE
#define SM_BH(buf) (2*ATILE + (buf)*2*ATILE)
#define SM_BL(buf) (3*ATILE + (buf)*2*ATILE)
#define SM_AF(buf) (6*ATILE + (buf)*(128*AFSTRIDE*4))
#define SM_TOTAL (6*ATILE + 2*(128*AFSTRIDE*4))   /* 98304 */

// Shared mainloop: cp.async double-buffered pipeline.
// A fragments (hi+lo) held across products; per n-pair: Bh -> AhBh+AlBh, Bl -> AhBl.
// 24 ldmatrix / 96 mma per chunk (was 36 / 96).
template<bool BNRELU>
__device__ __forceinline__ void gemm_mainloop(
    const float* __restrict__ A, const __nv_bfloat16* __restrict__ Bh,
    const __nv_bfloat16* __restrict__ Bl, const float* __restrict__ bnp,
    char* dsm, size_t rowbase, int ncb, int tid, int wm, int wn,
    float acc[2][8][4])
{
    int lane = tid & 31;
    int lr = tid >> 1;
    int cg = (tid & 1) * 16;
    int q3 = lane >> 3, rl = lane & 7;
    unsigned sb = (unsigned)__cvta_generic_to_shared(dsm);
    unsigned aoffA = (unsigned)(((wm*32 + (q3&1)*8 + rl) * RSTRIDE + (q3>>1)*8) * 2);
    unsigned aoffB = (unsigned)(((wn*64 + (q3>>1)*8 + rl) * RSTRIDE + (q3&1)*8) * 2);

    const float*         asrc0 = A  + (rowbase + lr)*256 + cg;
    const __nv_bfloat16* bhs0  = Bh + (size_t)(ncb + lr)*256 + cg;
    const __nv_bfloat16* bls0  = Bl + (size_t)(ncb + lr)*256 + cg;
    unsigned adst_r = (unsigned)((lr*AFSTRIDE + cg)*4);
    unsigned bdst_r = (unsigned)((lr*RSTRIDE  + cg)*2);

    // prologue: chunk 0 -> buffers 0
    {
        unsigned ad = sb + SM_AF(0) + adst_r;
        cpa16(ad,    asrc0);     cpa16(ad+16, asrc0+4);
        cpa16(ad+32, asrc0+8);   cpa16(ad+48, asrc0+12);
        unsigned bh = sb + SM_BH(0) + bdst_r;
        unsigned bl = sb + SM_BL(0) + bdst_r;
        cpa16(bh, bhs0); cpa16(bh+16, bhs0+8);
        cpa16(bl, bls0); cpa16(bl+16, bls0+8);
        CPA_COMMIT;
    }

    for (int ic = 0; ic < 8; ic++){
        int buf = ic & 1;
        CPA_WAIT0;
        __syncthreads();

        if (ic < 7){
            int kc1 = (ic+1)*KC;
            unsigned ad = sb + SM_AF(buf^1) + adst_r;
            const float* as = asrc0 + kc1;
            cpa16(ad,    as);    cpa16(ad+16, as+4);
            cpa16(ad+32, as+8);  cpa16(ad+48, as+12);
            unsigned bh = sb + SM_BH(buf^1) + bdst_r;
            unsigned bl = sb + SM_BL(buf^1) + bdst_r;
            cpa16(bh, bhs0 + kc1); cpa16(bh+16, bhs0 + kc1 + 8);
            cpa16(bl, bls0 + kc1); cpa16(bl+16, bls0 + kc1 + 8);
            CPA_COMMIT;
        }

        // convert A chunk ic: smem fp32 -> bnrelu -> bf16 hi/lo tiles
        {
            int kc0 = ic*KC;
            const float* af = (const float*)(dsm + SM_AF(buf)) + lr*AFSTRIDE + cg;
            float v[16];
            *(float4*)(v)    = *(const float4*)(af);
            *(float4*)(v+4)  = *(const float4*)(af+4);
            *(float4*)(v+8)  = *(const float4*)(af+8);
            *(float4*)(v+12) = *(const float4*)(af+12);
            unsigned hh[8], ll[8];
#pragma unroll
            for (int p=0;p<8;p++){
                float a0 = v[p*2], a1 = v[p*2+1];
                if (BNRELU){
                    int c = kc0 + cg + p*2;
                    a0 = fmaxf(0.f, fmaf(a0, bnp[c],   bnp[256+c]));
                    a1 = fmaxf(0.f, fmaf(a1, bnp[c+1], bnp[257+c]));
                }
                __nv_bfloat16 h0 = __float2bfloat16_rn(a0);
                __nv_bfloat16 h1 = __float2bfloat16_rn(a1);
                __nv_bfloat16 l0 = __float2bfloat16_rn(a0 - __bfloat162float(h0));
                __nv_bfloat16 l1 = __float2bfloat16_rn(a1 - __bfloat162float(h1));
                hh[p] = (unsigned)__bfloat16_as_ushort(h0) | ((unsigned)__bfloat16_as_ushort(h1)<<16);
                ll[p] = (unsigned)__bfloat16_as_ushort(l0) | ((unsigned)__bfloat16_as_ushort(l1)<<16);
            }
            unsigned short (*AsH)[RSTRIDE] = (unsigned short(*)[RSTRIDE])(dsm + SM_ASH);
            unsigned short (*AsL)[RSTRIDE] = (unsigned short(*)[RSTRIDE])(dsm + SM_ASL);
            *(uint4*)&AsH[lr][cg]   = make_uint4(hh[0],hh[1],hh[2],hh[3]);
            *(uint4*)&AsH[lr][cg+8] = make_uint4(hh[4],hh[5],hh[6],hh[7]);
            *(uint4*)&AsL[lr][cg]   = make_uint4(ll[0],ll[1],ll[2],ll[3]);
            *(uint4*)&AsL[lr][cg+8] = make_uint4(ll[4],ll[5],ll[6],ll[7]);
        }
        __syncthreads();

        unsigned aASH = sb + SM_ASH, aASL = sb + SM_ASL;
        unsigned aBH  = sb + SM_BH(buf), aBL = sb + SM_BL(buf);
#pragma unroll
        for (int ks=0; ks<KC; ks+=16){
            unsigned ah[2][4], al[2][4];
#pragma unroll
            for (int mt=0;mt<2;mt++){
                unsigned o = aoffA + (unsigned)((mt*16*RSTRIDE + ks)*2);
                ldmx4(ah[mt], aASH + o);
                ldmx4(al[mt], aASL + o);
            }
#pragma unroll
            for (int ntp=0;ntp<4;ntp++){
                unsigned bo = aoffB + (unsigned)((ntp*16*RSTRIDE + ks)*2);
                unsigned bb[4];
                ldmx4(bb, aBH + bo);
                mma_bf16(acc[0][2*ntp],   ah[0], bb);
                mma_bf16(acc[1][2*ntp],   ah[1], bb);
                mma_bf16(acc[0][2*ntp+1], ah[0], bb+2);
                mma_bf16(acc[1][2*ntp+1], ah[1], bb+2);
                mma_bf16(acc[0][2*ntp],   al[0], bb);
                mma_bf16(acc[1][2*ntp],   al[1], bb);
                mma_bf16(acc[0][2*ntp+1], al[0], bb+2);
                mma_bf16(acc[1][2*ntp+1], al[1], bb+2);
                ldmx4(bb, aBL + bo);
                mma_bf16(acc[0][2*ntp],   ah[0], bb);
                mma_bf16(acc[1][2*ntp],   ah[1], bb);
                mma_bf16(acc[0][2*ntp+1], ah[0], bb+2);
                mma_bf16(acc[1][2*ntp+1], ah[1], bb+2);
            }
        }
    }
}

// ---------------- GEMM (qkv / gamma1): store C, optional BN+fused stats ----------------
template<bool BNRELU, bool STATS>
__global__ __launch_bounds__(256, 2) void gemm_mma_kernel(
    const float* __restrict__ A,
    const __nv_bfloat16* __restrict__ Bh, const __nv_bfloat16* __restrict__ Bl,
    const float* __restrict__ bias, const float* __restrict__ bnp,
    float* __restrict__ C, float* __restrict__ psum, float* __restrict__ psq)
{
    extern __shared__ __align__(128) char dsm[];

    int tid = threadIdx.x, wid = tid >> 5, lane = tid & 31;
    int g = lane >> 2, t = lane & 3;
    int wm = wid & 3, wn = wid >> 2;
    const size_t rowbase = (size_t)blockIdx.x * 128;
    const int ncb = blockIdx.y * 128;

    float acc[2][8][4];
#pragma unroll
    for (int mt=0;mt<2;mt++)
#pragma unroll
        for (int nt=0;nt<8;nt++)
#pragma unroll
            for (int i=0;i<4;i++) acc[mt][nt][i]=0.f;

    gemm_mainloop<BNRELU>(A, Bh, Bl, bnp, dsm, rowbase, ncb, tid, wm, wn, acc);

#pragma unroll
    for (int nt=0;nt<8;nt++){
        int col = ncb + wn*64 + nt*8 + 2*t;
        float b0 = bias[col], b1 = bias[col+1];
#pragma unroll
        for (int mt=0;mt<2;mt++){
            acc[mt][nt][0]+=b0; acc[mt][nt][1]+=b1;
            acc[mt][nt][2]+=b0; acc[mt][nt][3]+=b1;
        }
    }
#pragma unroll
    for (int nt=0;nt<8;nt++){
        int col = ncb + wn*64 + nt*8 + 2*t;
#pragma unroll
        for (int mt=0;mt<2;mt++){
            size_t row = rowbase + wm*32 + mt*16 + g;
            *(float2*)&C[row*256 + col]     = make_float2(acc[mt][nt][0], acc[mt][nt][1]);
            *(float2*)&C[(row+8)*256 + col] = make_float2(acc[mt][nt][2], acc[mt][nt][3]);
        }
    }

    if (STATS){
        __syncthreads();
        float* sS = (float*)dsm;              // [4][128]
        float* sQ = sS + 512;
#pragma unroll
        for (int nt=0;nt<8;nt++){
            float s0=0.f,q0=0.f,s1=0.f,q1=0.f;
#pragma unroll
            for (int mt=0;mt<2;mt++){
                float v0=acc[mt][nt][0], v2=acc[mt][nt][2];
                float v1=acc[mt][nt][1], v3=acc[mt][nt][3];
                s0 += v0+v2;  q0 += v0*v0+v2*v2;
                s1 += v1+v3;  q1 += v1*v1+v3*v3;
            }
#pragma unroll
            for (int off=16; off>=4; off>>=1){
                s0 += __shfl_down_sync(0xffffffffu, s0, off);
                q0 += __shfl_down_sync(0xffffffffu, q0, off);
                s1 += __shfl_down_sync(0xffffffffu, s1, off);
                q1 += __shfl_down_sync(0xffffffffu, q1, off);
            }
            if (lane < 4){
                int c = wn*64 + nt*8 + 2*lane;
                sS[wm*128 + c]     = s0;  sS[wm*128 + c + 1] = s1;
                sQ[wm*128 + c]     = q0;  sQ[wm*128 + c + 1] = q1;
            }
        }
        __syncthreads();
        if (tid < 128){
            float s = sS[tid] + sS[128+tid] + sS[256+tid] + sS[384+tid];
            float q = sQ[tid] + sQ[128+tid] + sQ[256+tid] + sQ[384+tid];
            psum[blockIdx.x*256 + ncb + tid] = s;
            psq [blockIdx.x*256 + ncb + tid] = q;
        }
    }
}

// ---------------- fused gamma2 + softmax(K) + weighted output ----------------
#define VSTRIDE 132
__global__ __launch_bounds__(256, 2) void gemm_attn_kernel(
    const float* __restrict__ A,
    const __nv_bfloat16* __restrict__ Bh, const __nv_bfloat16* __restrict__ Bl,
    const float* __restrict__ bias, const float* __restrict__ bnp,
    const float* __restrict__ d2w, const float* __restrict__ d2b,
    float* __restrict__ out)
{
    extern __shared__ __align__(128) char dsm[];
    float* Vs = (float*)dsm;                     // reused after mainloop: 128 x VSTRIDE

    int tid = threadIdx.x, wid = tid >> 5, lane = tid & 31;
    int g = lane >> 2, t = lane & 3;
    int wm = wid & 3, wn = wid >> 2;
    const size_t rowbase = (size_t)blockIdx.x * 128;
    const int ncb = blockIdx.y * 128;

    float acc[2][8][4];
#pragma unroll
    for (int mt=0;mt<2;mt++)
#pragma unroll
        for (int nt=0;nt<8;nt++)
#pragma unroll
            for (int i=0;i<4;i++) acc[mt][nt][i]=0.f;

    gemm_mainloop<true>(A, Bh, Bl, bnp, dsm, rowbase, ncb, tid, wm, wn, acc);

    // bias -> logits
#pragma unroll
    for (int nt=0;nt<8;nt++){
        int col = ncb + wn*64 + nt*8 + 2*t;
        float b0 = bias[col], b1 = bias[col+1];
#pragma unroll
        for (int mt=0;mt<2;mt++){
            acc[mt][nt][0]+=b0; acc[mt][nt][1]+=b1;
            acc[mt][nt][2]+=b0; acc[mt][nt][3]+=b1;
        }
    }

    __syncthreads();   // tiles no longer needed; reuse as Vs

    // stage gathered v rows
    {
        int r = tid >> 1;
        int half = (tid & 1) * 64;
        size_t grow = rowbase + r;
        int gpt = (int)(grow >> 4);
        int b = gpt >> 12;
        int j = g_idx[grow];
        const float* vp = g_vf + ((size_t)(b*NP + j))*256 + ncb + half;
        float* dst = Vs + r*VSTRIDE + half;
#pragma unroll
        for (int i=0;i<16;i++)
            *(float4*)(dst + i*4) = *(const float4*)(vp + i*4);
    }

    // softmax over K — register + shfl only
#pragma unroll
    for (int mt=0;mt<2;mt++)
#pragma unroll
    for (int nt=0;nt<8;nt++){
        float a0=acc[mt][nt][0], a1=acc[mt][nt][1], a2=acc[mt][nt][2], a3=acc[mt][nt][3];
        float m0 = fmaxf(a0,a2), m1 = fmaxf(a1,a3);
#pragma unroll
        for (int mk=4; mk<=16; mk<<=1){
            m0 = fmaxf(m0, __shfl_xor_sync(0xffffffffu, m0, mk));
            m1 = fmaxf(m1, __shfl_xor_sync(0xffffffffu, m1, mk));
        }
        float e0=expf(a0-m0), e2=expf(a2-m0), e1=expf(a1-m1), e3=expf(a3-m1);
        float s0=e0+e2, s1=e1+e3;
#pragma unroll
        for (int mk=4; mk<=16; mk<<=1){
            s0 += __shfl_xor_sync(0xffffffffu, s0, mk);
            s1 += __shfl_xor_sync(0xffffffffu, s1, mk);
        }
        float i0=1.f/s0, i1=1.f/s1;
        acc[mt][nt][0]=e0*i0; acc[mt][nt][1]=e1*i1;
        acc[mt][nt][2]=e2*i0; acc[mt][nt][3]=e3*i1;
    }

    // u vectors for this thread's 2x2 k-rows
    float3 uv[2][2];
#pragma unroll
    for (int mt=0;mt<2;mt++)
#pragma unroll
    for (int kk=0;kk<2;kk++){
        size_t r = rowbase + wm*32 + mt*16 + g + kk*8;
        uv[mt][kk] = make_float3(g_u[r*3], g_u[r*3+1], g_u[r*3+2]);
    }

    __syncthreads();   // Vs ready

    // weighted output
#pragma unroll
    for (int nt=0;nt<8;nt++){
        int c0 = wn*64 + nt*8 + 2*t;
        int gc = ncb + c0;
        float w0a=d2w[gc],   w1a=d2w[256+gc],   w2a=d2w[512+gc],   ba=d2b[gc];
        float w0b=d2w[gc+1], w1b=d2w[257+gc],   w2b=d2w[513+gc],   bb=d2b[gc+1];
#pragma unroll
        for (int mt=0;mt<2;mt++){
            float o0=0.f, o1=0.f;
#pragma unroll
            for (int kk=0;kk<2;kk++){
                int r = wm*32 + mt*16 + g + kk*8;
                float2 v = *(const float2*)&Vs[r*VSTRIDE + c0];
                float3 u = uv[mt][kk];
                float pea = u.x*w0a + u.y*w1a + u.z*w2a + ba;
                float peb = u.x*w0b + u.y*w1b + u.z*w2b + bb;
                o0 += acc[mt][nt][kk*2+0] * (v.x + pea);
                o1 += acc[mt][nt][kk*2+1] * (v.y + peb);
            }
#pragma unroll
            for (int mk=4; mk<=16; mk<<=1){
                o0 += __shfl_xor_sync(0xffffffffu, o0, mk);
                o1 += __shfl_xor_sync(0xffffffffu, o1, mk);
            }
            if (g == 0){
                size_t pt = (rowbase >> 4) + 2*wm + mt;
                *(float2*)&out[pt*256 + gc] = make_float2(o0, o1);
            }
        }
    }
}

// ---------------- finalize per-channel BN over 256 channels ----------------
__global__ __launch_bounds__(256) void bnfin_kernel(const float* __restrict__ psum,
                                                    const float* __restrict__ psq, int P,
                                                    const float* __restrict__ g,
                                                    const float* __restrict__ beta,
                                                    float* __restrict__ outp)
{
    int c = threadIdx.x;
    double s=0.0,q=0.0;
    for (int i=0;i<P;i++){ s+=psum[i*NC+c]; q+=psq[i*NC+c]; }
    double m = s/(double)NROWS;
    double v = q/(double)NROWS - m*m;
    double sc = (double)g[c] / sqrt(v+1e-5);
    outp[c]    = (float)sc;
    outp[NC+c] = (float)((double)beta[c] - m*sc);
}

// ---------------- h producer ----------------
__global__ __launch_bounds__(256) void hprod_kernel(
    const float* __restrict__ xyz, const float* __restrict__ d1w, const float* __restrict__ d1b,
    const float* __restrict__ d2w, const float* __restrict__ d2b)
{
    __shared__ float su[NK*3];
    __shared__ int   sj[NK];
    int c = threadIdx.x;
    float d2c0 = d2w[c], d2c1 = d2w[256+c], d2c2 = d2w[512+c], d2bc = d2b[c];
    float s=0.f, q=0.f;
    for (int pp=0; pp<32; pp++){
        int pt = blockIdx.x*32 + pp;
        int b  = pt >> 12;
        if (c < NK){
            int k = c;
            int j = g_idx[pt*NK+k];
            sj[k]=j;
            float r0 = xyz[pt*3+0]-xyz[(b*NP+j)*3+0];
            float r1 = xyz[pt*3+1]-xyz[(b*NP+j)*3+1];
            float r2 = xyz[pt*3+2]-xyz[(b*NP+j)*3+2];
#pragma unroll
            for (int d=0;d<3;d++){
                float t  = r0*d1w[d] + r1*d1w[3+d] + r2*d1w[6+d] + d1b[d];
                float uu = fmaxf(0.f, fmaf(t, g_bnd[d], g_bnd[3+d]));
                su[k*3+d]=uu;
                g_u[(pt*NK+k)*3+d]=uu;
            }
        }
        __syncthreads();
        float qv = g_q[pt*NC + c];
#pragma unroll
        for (int k=0;k<NK;k++){
            int j = sj[k];
            float kv = g_kf[(b*NP+j)*NC + c];
            float pe = su[k*3]*d2c0 + su[k*3+1]*d2c1 + su[k*3+2]*d2c2 + d2bc;
            float h = qv - kv + pe;
            g_h[(size_t)(pt*NK+k)*NC + c] = h;
            s += h; q += h*h;
        }
        __syncthreads();
    }
    g_ps1[blockIdx.x*NC+c]=s;
    g_pq1[blockIdx.x*NC+c]=q;
}

// ---------------- host launcher ----------------
extern "C" void kernel_launch(void* const* d_in, const int* in_sizes, int n_in,
                              void* d_out, int out_size)
{
    const float* xyz  = (const float*)d_in[0];
    const float* feat = (const float*)d_in[1];
    const float* wq   = (const float*)d_in[2];  const float* bq  = (const float*)d_in[3];
    const float* wk   = (const float*)d_in[4];  const float* bk  = (const float*)d_in[5];
    const float* wv   = (const float*)d_in[6];  const float* bv  = (const float*)d_in[7];
    const float* d1w  = (const float*)d_in[8];  const float* d1b = (const float*)d_in[9];
    const float* bndg = (const float*)d_in[10]; const float* bndb= (const float*)d_in[11];
    const float* d2w  = (const float*)d_in[12]; const float* d2b = (const float*)d_in[13];
    const float* g1g  = (const float*)d_in[14]; const float* g1bt= (const float*)d_in[15];
    const float* g1w  = (const float*)d_in[16]; const float* g1b = (const float*)d_in[17];
    const float* g2g  = (const float*)d_in[18]; const float* g2bt= (const float*)d_in[19];
    const float* g2w  = (const float*)d_in[20]; const float* g2b = (const float*)d_in[21];
    float* out = (float*)d_out;

    float *p_q,*p_kf,*p_vf,*p_h,*p_h2,*p_bn1,*p_bn2,*p_ps1,*p_pq1,*p_ps2,*p_pq2;
    __nv_bfloat16 *p_bh1,*p_bl1,*p_bh2,*p_bl2,*p_bhq,*p_blq,*p_bhk,*p_blk,*p_bhv,*p_blv;
    cudaGetSymbolAddress((void**)&p_q,  g_q);
    cudaGetSymbolAddress((void**)&p_kf, g_kf);
    cudaGetSymbolAddress((void**)&p_vf, g_vf);
    cudaGetSymbolAddress((void**)&p_h,  g_h);
    cudaGetSymbolAddress((void**)&p_h2, g_h2);
    cudaGetSymbolAddress((void**)&p_bn1,g_bn1);
    cudaGetSymbolAddress((void**)&p_bn2,g_bn2);
    cudaGetSymbolAddress((void**)&p_ps1,g_ps1);
    cudaGetSymbolAddress((void**)&p_pq1,g_pq1);
    cudaGetSymbolAddress((void**)&p_ps2,g_ps2);
    cudaGetSymbolAddress((void**)&p_pq2,g_pq2);
    cudaGetSymbolAddress((void**)&p_bh1,g_bh1);
    cudaGetSymbolAddress((void**)&p_bl1,g_bl1);
    cudaGetSymbolAddress((void**)&p_bh2,g_bh2);
    cudaGetSymbolAddress((void**)&p_bl2,g_bl2);
    cudaGetSymbolAddress((void**)&p_bhq,g_bhq);
    cudaGetSymbolAddress((void**)&p_blq,g_blq);
    cudaGetSymbolAddress((void**)&p_bhk,g_bhk);
    cudaGetSymbolAddress((void**)&p_blk,g_blk);
    cudaGetSymbolAddress((void**)&p_bhv,g_bhv);
    cudaGetSymbolAddress((void**)&p_blv,g_blv);

    cudaFuncSetAttribute(gemm_mma_kernel<false,false>,
                         cudaFuncAttributeMaxDynamicSharedMemorySize, SM_TOTAL);
    cudaFuncSetAttribute(gemm_mma_kernel<true,true>,
                         cudaFuncAttributeMaxDynamicSharedMemorySize, SM_TOTAL);
    cudaFuncSetAttribute(gemm_attn_kernel,
                         cudaFuncAttributeMaxDynamicSharedMemorySize, SM_TOTAL);

    // Launch order: slot #4 (ncu capture) = gemm_k with the new mainloop.
    knn_kernel<<<dim3(NP/8, NB), 256>>>(xyz);
    bprep5_kernel<<<dim3(NC,5),NC>>>(g1w, g2w, wq, wk, wv);
    gemm_mma_kernel<false,false><<<dim3(NPTS/128,2),256,SM_TOTAL>>>(feat, p_bhq, p_blq, bq, nullptr, p_q,  nullptr, nullptr);
    gemm_mma_kernel<false,false><<<dim3(NPTS/128,2),256,SM_TOTAL>>>(feat, p_bhk, p_blk, bk, nullptr, p_kf, nullptr, nullptr);
    gemm_mma_kernel<false,false><<<dim3(NPTS/128,2),256,SM_TOTAL>>>(feat, p_bhv, p_blv, bv, nullptr, p_vf, nullptr, nullptr);
    dstat_kernel<<<512,256>>>(xyz, d1w, d1b);
    dfin_kernel<<<1,32>>>(bndg, bndb);
    hprod_kernel<<<512,256>>>(xyz, d1w, d1b, d2w, d2b);
    bnfin_kernel<<<1,256>>>(p_ps1, p_pq1, 512, g1g, g1bt, p_bn1);
    gemm_mma_kernel<true,true><<<dim3(NROWS/128,2),256,SM_TOTAL>>>(p_h, p_bh1, p_bl1, g1b, p_bn1, p_h2, p_ps2, p_pq2);
    bnfin_kernel<<<1,256>>>(p_ps2, p_pq2, 2048, g2g, g2bt, p_bn2);
    gemm_attn_kernel<<<dim3(NROWS/128,2),256,SM_TOTAL>>>(
        p_h2, p_bh2, p_bl2, g2b, p_bn2, d2w, d2b, out);
}